// round 11
// baseline (speedup 1.0000x reference)
#include <cuda_runtime.h>
#include <cuda_bf16.h>
#include <cstdint>
#include <cstddef>

#define NN 50000
#define EE 800000

// ---------------- static scratch ----------------
__device__ float g_XNI[(size_t)NN * 128];
__device__ float g_XNJ[(size_t)NN * 128];
__device__ float g_H  [(size_t)NN * 128];
__device__ float g_X2 [(size_t)NN * 128];
__device__ float g_X3 [(size_t)NN * 32];
__device__ float g_score[EE];
__device__ float g_ex[EE];
__device__ int   g_menc[NN];
__device__ float g_ssum[NN];
__device__ float g_bn2[32], g_bias2[32], g_attn2[32];

__device__ __nv_bfloat16 g_F1P[2][(size_t)EE * 128];
__device__ __nv_bfloat16 g_F2P[2][(size_t)EE * 32];
#define WL1 (128 * 128)
#define WL2 (32 * 128)
#define WL3 (64 * 32)
__device__ __nv_bfloat16 g_wts[2][4 * WL1 + 4 * WL2 + 3 * WL3];

// ---------------- helpers ----------------
__device__ __forceinline__ uint32_t pk(float a, float b) {
    __nv_bfloat162 h = __floats2bfloat162_rn(a, b);
    return *(uint32_t*)&h;
}
__device__ __forceinline__ float bfe(float v) {
    return __bfloat162float(__float2bfloat16_rn(v));
}
__device__ __forceinline__ void mma16(float d[4], const uint32_t a[4], const uint32_t b[2]) {
    asm volatile(
        "mma.sync.aligned.m16n8k16.row.col.f32.bf16.bf16.f32 "
        "{%0,%1,%2,%3}, {%4,%5,%6,%7}, {%8,%9}, {%0,%1,%2,%3};\n"
        : "+f"(d[0]), "+f"(d[1]), "+f"(d[2]), "+f"(d[3])
        : "r"(a[0]), "r"(a[1]), "r"(a[2]), "r"(a[3]), "r"(b[0]), "r"(b[1]));
}
__device__ __forceinline__ void ldsm4(uint32_t r[4], uint32_t addr) {
    asm volatile("ldmatrix.sync.aligned.m8n8.x4.shared.b16 {%0,%1,%2,%3}, [%4];"
        : "=r"(r[0]), "=r"(r[1]), "=r"(r[2]), "=r"(r[3]) : "r"(addr));
}
__device__ __forceinline__ void cpa16(uint32_t saddr, const void* g) {
    asm volatile("cp.async.ca.shared.global [%0], [%1], 16;" :: "r"(saddr), "l"(g));
}
__device__ __forceinline__ void cp_commit() {
    asm volatile("cp.async.commit_group;");
}
template<int N>
__device__ __forceinline__ void cp_wait() {
    asm volatile("cp.async.wait_group %0;" :: "n"(N) : "memory");
}

// ---------------- weight conversion: f32 [K][N] -> transposed planes [Np][Kp] ----------------
struct WJob { const float* w; int off, K, N, Kp, Np; };
struct WJobs { WJob j[11]; };
__global__ void conv_wt(WJobs js, __nv_bfloat16* hiB, __nv_bfloat16* loB) {
    WJob jb = js.j[blockIdx.y];
    int i = blockIdx.x * blockDim.x + threadIdx.x;
    if (i >= jb.Np * jb.Kp) return;
    int n = i / jb.Kp, k = i % jb.Kp;
    float v = (n < jb.N && k < jb.K) ? jb.w[k * jb.N + n] : 0.0f;
    __nv_bfloat16 h = __float2bfloat16_rn(v);
    hiB[jb.off + i] = h;
    loB[jb.off + i] = __float2bfloat16_rn(v - __bfloat162float(h));
}

struct VJob { const float* in; float* out; int C, nC; };
struct VJobs { VJob j[3]; };
__global__ void pad_vec(VJobs js) {
    VJob p = js.j[blockIdx.y];
    int i = threadIdx.x;
    if (i < p.nC) p.out[i] = (i < p.C) ? p.in[i] : 0.0f;
}

// ---------------- GEMM: B smem-resident, 3-pass MMA (no acc chains), bf16x3 ----------------
// AF32=1: A is f32 [M][K], converted in-kernel. AF32=0: A is bf16 hi/lo planes.
// MODE 0: C = A@B (+bias). MODE 1: F planes + score. MODE 2: C = leaky(...).
template<int BN, int KT, int WM, int WN, int MODE, int AF32>
__global__ __launch_bounds__(256, 2) void gemm_pl(
    const void* __restrict__ Apv, const void* __restrict__ Apv2,
    const __nv_bfloat16* __restrict__ Bhi, const __nv_bfloat16* __restrict__ Blo,
    float* __restrict__ C, __nv_bfloat16* __restrict__ Fhi, __nv_bfloat16* __restrict__ Flo,
    const float* __restrict__ bias,
    const float* __restrict__ XNI, const float* __restrict__ XNJ,
    const int* __restrict__ src, const int* __restrict__ dst,
    const float* __restrict__ attn, float* __restrict__ score, int M)
{
    constexpr int BM = 128, T = KT / 16, NS = AF32 ? 2 : 3;
    constexpr int BS = KT * 2 + 16;            // B row stride (bytes), conflict-free
    constexpr int MT = WM / 16, NT = WN / 8;
    constexpr int WARPS_N = BN / WN;
    static_assert((BM / WM) * (BN / WN) == 8, "need 8 warps");
    static_assert(NT % 2 == 0, "paired B ldsm4");

    extern __shared__ __align__(16) char dynsm[];
    char* sBp = dynsm + NS * 2 * BM * 48;
    float* s_sc = (float*)(sBp + 2 * BN * BS);

    const int tid  = threadIdx.x;
    const int warp = tid >> 5, lane = tid & 31;
    const int gid  = lane >> 2, tig = lane & 3;
    const int wm   = warp / WARPS_N, wn = warp % WARPS_N;
    const int rowW = wm * WM, colW = wn * WN;
    const int row0 = blockIdx.x * BM;

    const uint32_t aBase = (uint32_t)__cvta_generic_to_shared(dynsm);
    const uint32_t bBase = (uint32_t)__cvta_generic_to_shared(sBp);

    const float* Af = (const float*)Apv;
    const __nv_bfloat16* Ahi = (const __nv_bfloat16*)Apv;
    const __nv_bfloat16* Alo = (const __nv_bfloat16*)Apv2;

    if (MODE == 1 && tid < BM) s_sc[tid] = 0.0f;

    float acc[MT][NT][4];
    #pragma unroll
    for (int i = 0; i < MT; i++)
        #pragma unroll
        for (int j = 0; j < NT; j++)
            #pragma unroll
            for (int t = 0; t < 4; t++) acc[i][j][t] = 0.0f;

    const int lrA = lane & 15;
    const int kofA = ((lane >> 4) & 1) * 16;
    // paired-B ldsm4 lane mapping: lanes 0-7 (j0,k0), 8-15 (j0,k16B), 16-23 (j1,k0), 24-31 (j1,k16B)
    const int bRow = ((lane >> 4) & 1) * 8 + (lane & 7);
    const int kofB = ((lane >> 3) & 1) * 16;

    const int arow = tid >> 1, ahalf = tid & 1;
    float areg[8];

    auto issueB = [&]() {
        constexpr int CH = KT / 8;
        #pragma unroll
        for (int c = tid; c < 2 * BN * CH; c += 256) {
            int pl = c / (BN * CH);
            int rem = c - pl * BN * CH;
            int n = rem / CH, ch = rem - n * CH;
            const __nv_bfloat16* g = (pl ? Blo : Bhi) + (size_t)n * KT + ch * 8;
            cpa16(bBase + (uint32_t)((pl * BN + n) * BS + ch * 16), g);
        }
    };
    auto loadAf32 = [&](int t) {
        int gr = row0 + arow;
        if (gr < M) {
            const float* p = &Af[(size_t)gr * KT + t * 16 + ahalf * 8];
            float4 q0 = *(const float4*)p;
            float4 q1 = *(const float4*)(p + 4);
            areg[0] = q0.x; areg[1] = q0.y; areg[2] = q0.z; areg[3] = q0.w;
            areg[4] = q1.x; areg[5] = q1.y; areg[6] = q1.z; areg[7] = q1.w;
        } else {
            #pragma unroll
            for (int u = 0; u < 8; u++) areg[u] = 0.0f;
        }
    };
    auto stsA = [&](int s) {
        __nv_bfloat16 h[8], l[8];
        #pragma unroll
        for (int u = 0; u < 8; u++) {
            h[u] = __float2bfloat16_rn(areg[u]);
            l[u] = __float2bfloat16_rn(areg[u] - __bfloat162float(h[u]));
        }
        __nv_bfloat16* base = (__nv_bfloat16*)dynsm;
        *(uint4*)&base[((s * 2 + 0) * BM + arow) * 24 + ahalf * 8] = *(uint4*)h;
        *(uint4*)&base[((s * 2 + 1) * BM + arow) * 24 + ahalf * 8] = *(uint4*)l;
    };
    auto issueApl = [&](int t, int s) {
        #pragma unroll
        for (int c = tid; c < BM * 4; c += 256) {
            int half = c & 1, pl = (c >> 1) & 1, r = c >> 2;
            const __nv_bfloat16* g = (pl ? Alo : Ahi) + (size_t)(row0 + r) * KT + t * 16 + half * 8;
            cpa16(aBase + (uint32_t)(((s * 2 + pl) * BM + r) * 48 + half * 16), g);
        }
    };
    auto mmaStage = [&](int s, int t) {
        uint32_t ah[MT][4], al[MT][4], bh[NT][2], bl[NT][2];
        uint32_t aOff = aBase + (uint32_t)(s * 2 * BM * 48);
        // A hi fragments
        #pragma unroll
        for (int i = 0; i < MT; i++)
            ldsm4(ah[i], aOff + (uint32_t)((rowW + i * 16 + lrA) * 48) + kofA);
        // B hi+lo fragments, two n-columns per ldsm4
        #pragma unroll
        for (int jp = 0; jp < NT / 2; jp++) {
            uint32_t rb = bBase + (uint32_t)((colW + jp * 16 + bRow) * BS) + (uint32_t)(t * 32) + kofB;
            uint32_t r[4];
            ldsm4(r, rb);
            bh[2 * jp][0] = r[0]; bh[2 * jp][1] = r[1];
            bh[2 * jp + 1][0] = r[2]; bh[2 * jp + 1][1] = r[3];
            ldsm4(r, rb + (uint32_t)(BN * BS));
            bl[2 * jp][0] = r[0]; bl[2 * jp][1] = r[1];
            bl[2 * jp + 1][0] = r[2]; bl[2 * jp + 1][1] = r[3];
        }
        // pass 1: ah * bh  (each acc touched once per pass -> no RAW chains)
        #pragma unroll
        for (int i = 0; i < MT; i++)
            #pragma unroll
            for (int j = 0; j < NT; j++)
                mma16(acc[i][j], ah[i], bh[j]);
        // A lo fragments (deferred to cap register live-range)
        #pragma unroll
        for (int i = 0; i < MT; i++)
            ldsm4(al[i], aOff + (uint32_t)(BM * 48) + (uint32_t)((rowW + i * 16 + lrA) * 48) + kofA);
        // pass 2: ah * bl
        #pragma unroll
        for (int i = 0; i < MT; i++)
            #pragma unroll
            for (int j = 0; j < NT; j++)
                mma16(acc[i][j], ah[i], bl[j]);
        // pass 3: al * bh
        #pragma unroll
        for (int i = 0; i < MT; i++)
            #pragma unroll
            for (int j = 0; j < NT; j++)
                mma16(acc[i][j], al[i], bh[j]);
    };

    if (AF32) {
        loadAf32(0);
        issueB(); cp_commit();
        stsA(0);
        cp_wait<0>();
        __syncthreads();
        for (int t = 0; t < T; t++) {
            int s = t & 1;
            if (t + 1 < T) loadAf32(t + 1);
            mmaStage(s, t);
            if (t + 1 < T) stsA(1 - s);
            __syncthreads();
        }
    } else {
        issueB(); issueApl(0, 0); cp_commit();
        if (T > 1) { issueApl(1, 1); cp_commit(); }
        for (int t = 0; t < T; t++) {
            if (t < T - 1) cp_wait<1>(); else cp_wait<0>();
            __syncthreads();
            mmaStage(t % 3, t);
            if (t + 2 < T) { issueApl(t + 2, (t + 2) % 3); cp_commit(); }
        }
    }

    // ---------------- epilogue ----------------
    if (MODE == 0) {
        #pragma unroll
        for (int i = 0; i < MT; i++) {
            int gr1 = row0 + rowW + i * 16 + gid;
            int gr2 = gr1 + 8;
            #pragma unroll
            for (int j = 0; j < NT; j++) {
                int c = colW + j * 8 + 2 * tig;
                float b0 = bias ? bias[c] : 0.0f;
                float b1 = bias ? bias[c + 1] : 0.0f;
                if (gr1 < M)
                    *(float2*)&C[(size_t)gr1 * BN + c] =
                        make_float2(acc[i][j][0] + b0, acc[i][j][1] + b1);
                if (gr2 < M)
                    *(float2*)&C[(size_t)gr2 * BN + c] =
                        make_float2(acc[i][j][2] + b0, acc[i][j][3] + b1);
            }
        }
    } else {
        #pragma unroll
        for (int i = 0; i < MT; i++) {
            int lr1 = rowW + i * 16 + gid, lr2 = lr1 + 8;
            int gr1 = row0 + lr1, gr2 = row0 + lr2;
            int sn1 = src[gr1], dn1 = dst[gr1];
            int sn2 = src[gr2], dn2 = dst[gr2];
            float sc1 = 0.0f, sc2 = 0.0f;
            #pragma unroll
            for (int j = 0; j < NT; j++) {
                int c = colW + j * 8 + 2 * tig;
                float b0 = bias[c], b1 = bias[c + 1];
                float2 xi1 = *(const float2*)&XNI[(size_t)sn1 * BN + c];
                float2 xj1 = *(const float2*)&XNJ[(size_t)dn1 * BN + c];
                float o0 = acc[i][j][0] + xi1.x + xj1.x + b0;
                float o1 = acc[i][j][1] + xi1.y + xj1.y + b1;
                o0 = o0 > 0.f ? o0 : 0.01f * o0;
                o1 = o1 > 0.f ? o1 : 0.01f * o1;
                float2 xi2 = *(const float2*)&XNI[(size_t)sn2 * BN + c];
                float2 xj2 = *(const float2*)&XNJ[(size_t)dn2 * BN + c];
                float p0 = acc[i][j][2] + xi2.x + xj2.x + b0;
                float p1 = acc[i][j][3] + xi2.y + xj2.y + b1;
                p0 = p0 > 0.f ? p0 : 0.01f * p0;
                p1 = p1 > 0.f ? p1 : 0.01f * p1;
                if (MODE == 1) {
                    *(uint32_t*)&Fhi[(size_t)gr1 * BN + c] = pk(o0, o1);
                    *(uint32_t*)&Flo[(size_t)gr1 * BN + c] = pk(o0 - bfe(o0), o1 - bfe(o1));
                    *(uint32_t*)&Fhi[(size_t)gr2 * BN + c] = pk(p0, p1);
                    *(uint32_t*)&Flo[(size_t)gr2 * BN + c] = pk(p0 - bfe(p0), p1 - bfe(p1));
                    float a0 = attn[c], a1 = attn[c + 1];
                    sc1 += o0 * a0 + o1 * a1;
                    sc2 += p0 * a0 + p1 * a1;
                } else {
                    *(float2*)&C[(size_t)gr1 * BN + c] = make_float2(o0, o1);
                    *(float2*)&C[(size_t)gr2 * BN + c] = make_float2(p0, p1);
                }
            }
            if (MODE == 1) {
                sc1 += __shfl_xor_sync(0xffffffffu, sc1, 1);
                sc1 += __shfl_xor_sync(0xffffffffu, sc1, 2);
                sc2 += __shfl_xor_sync(0xffffffffu, sc2, 1);
                sc2 += __shfl_xor_sync(0xffffffffu, sc2, 2);
                if (tig == 0) {
                    atomicAdd(&s_sc[lr1], sc1);
                    atomicAdd(&s_sc[lr2], sc2);
                }
            }
        }
        if (MODE == 1) {
            __syncthreads();
            if (tid < BM) score[row0 + tid] = s_sc[tid];
        }
    }
}

// ---------------- segment softmax over dst ----------------
__device__ __forceinline__ int enc_f(float f) {
    int i = __float_as_int(f);
    return i >= 0 ? i : (i ^ 0x7fffffff);
}
__device__ __forceinline__ float dec_f(int i) {
    return __int_as_float(i >= 0 ? i : (i ^ 0x7fffffff));
}

__global__ void seg_max(const float* __restrict__ score, const int* __restrict__ dst,
                        int* __restrict__ menc, int E) {
    int e = blockIdx.x * blockDim.x + threadIdx.x;
    if (e >= E) return;
    atomicMax(&menc[dst[e]], enc_f(score[e]));
}

__global__ void seg_expsum(const float* __restrict__ score, const int* __restrict__ dst,
                           const int* __restrict__ menc, float* __restrict__ ex,
                           float* __restrict__ ssum, int E) {
    int e = blockIdx.x * blockDim.x + threadIdx.x;
    if (e >= E) return;
    int d = dst[e];
    float ev = expf(score[e] - dec_f(menc[d]));
    ex[e] = ev;
    atomicAdd(&ssum[d], ev);
}

template<int DO>
__global__ void aggregate_k(const float* __restrict__ ex, const float* __restrict__ ssum,
                            const float* __restrict__ H, const int* __restrict__ src,
                            const int* __restrict__ dst, float* __restrict__ out, int E) {
    constexpr int L = DO / 4;
    long long gt = (long long)blockIdx.x * blockDim.x + threadIdx.x;
    int e = (int)(gt / L), l = (int)(gt % L);
    if (e >= E) return;
    int dn = dst[e];
    float a = ex[e] / ssum[dn];
    float4 h = *(const float4*)&H[(size_t)src[e] * DO + l * 4];
    float* p = &out[(size_t)dn * DO + l * 4];
    asm volatile("red.global.add.v4.f32 [%0], {%1,%2,%3,%4};"
                 :: "l"(p), "f"(h.x * a), "f"(h.y * a), "f"(h.z * a), "f"(h.w * a)
                 : "memory");
}

// ---------------- host ----------------
static inline constexpr int smemSz(int BN, int KT, int AF32) {
    return (AF32 ? 2 : 3) * 2 * 128 * 48 + 2 * BN * (KT * 2 + 16) + 512;
}

extern "C" void kernel_launch(void* const* d_in, const int* in_sizes, int n_in,
                              void* d_out, int out_size) {
    const float* x    = (const float*)d_in[0];
    const float* e    = (const float*)d_in[1];
    const int*   src  = (const int*)d_in[2];
    const int*   dst  = (const int*)d_in[3];

    const float* W_n1  = (const float*)d_in[4];
    const float* b_n1  = (const float*)d_in[5];
    const float* W_ni1 = (const float*)d_in[6];
    const float* W_nj1 = (const float*)d_in[7];
    const float* W_f1  = (const float*)d_in[8];
    const float* attn1 = (const float*)d_in[9];
    const float* bias1 = (const float*)d_in[10];

    const float* W_n2  = (const float*)d_in[11];
    const float* b_n2  = (const float*)d_in[12];
    const float* W_ni2 = (const float*)d_in[13];
    const float* W_nj2 = (const float*)d_in[14];
    const float* W_f2  = (const float*)d_in[15];
    const float* attn2 = (const float*)d_in[16];
    const float* bias2 = (const float*)d_in[17];

    const float* W_ni3 = (const float*)d_in[20];
    const float* W_nj3 = (const float*)d_in[21];
    const float* W_f3  = (const float*)d_in[22];
    const float* bias3 = (const float*)d_in[24];

    float* out = (float*)d_out;

    float *XNI, *XNJ, *H, *X2, *X3, *score, *ex, *ssum, *bn2, *bias2p, *attn2p;
    int* menc;
    __nv_bfloat16 *F1P, *F2P, *wts;
    cudaGetSymbolAddress((void**)&XNI, g_XNI);
    cudaGetSymbolAddress((void**)&XNJ, g_XNJ);
    cudaGetSymbolAddress((void**)&H,   g_H);
    cudaGetSymbolAddress((void**)&X2,  g_X2);
    cudaGetSymbolAddress((void**)&X3,  g_X3);
    cudaGetSymbolAddress((void**)&score, g_score);
    cudaGetSymbolAddress((void**)&ex,  g_ex);
    cudaGetSymbolAddress((void**)&ssum, g_ssum);
    cudaGetSymbolAddress((void**)&menc, g_menc);
    cudaGetSymbolAddress((void**)&bn2,  g_bn2);
    cudaGetSymbolAddress((void**)&bias2p, g_bias2);
    cudaGetSymbolAddress((void**)&attn2p, g_attn2);
    cudaGetSymbolAddress((void**)&F1P, g_F1P);
    cudaGetSymbolAddress((void**)&F2P, g_F2P);
    cudaGetSymbolAddress((void**)&wts, g_wts);

    const size_t ePN  = (size_t)EE * 128;
    const size_t F2PN = (size_t)EE * 32;
    const size_t WTN  = 4 * WL1 + 4 * WL2 + 3 * WL3;
    __nv_bfloat16 *wtH = wts, *wtL = wts + WTN;
    const int oWn1 = 0 * WL1, oWni1 = 1 * WL1, oWnj1 = 2 * WL1, oWf1 = 3 * WL1;
    const int base2 = 4 * WL1;
    const int oWn2 = base2, oWni2 = base2 + WL2, oWnj2 = base2 + 2 * WL2, oWf2 = base2 + 3 * WL2;
    const int base3 = base2 + 4 * WL2;
    const int oWni3 = base3, oWnj3 = base3 + WL3, oWf3 = base3 + 2 * WL3;

    const int Nn = NN, Ee = EE;
    const int nodeGrid = (Nn + 127) / 128;
    const int edgeGrid = Ee / 128;
    const int perThread = (Ee + 255) / 256;

    constexpr int S1  = smemSz(128, 128, 1);
    constexpr int S2n = smemSz(32, 128, 1);
    constexpr int S2e = smemSz(32, 128, 0);
    constexpr int S3n = smemSz(64, 32, 1);
    constexpr int S3e = smemSz(64, 32, 0);
    cudaFuncSetAttribute(gemm_pl<128, 128, 64, 32, 0, 1>, cudaFuncAttributeMaxDynamicSharedMemorySize, S1);
    cudaFuncSetAttribute(gemm_pl<128, 128, 64, 32, 1, 1>, cudaFuncAttributeMaxDynamicSharedMemorySize, S1);
    cudaFuncSetAttribute(gemm_pl<32, 128, 16, 32, 1, 0>, cudaFuncAttributeMaxDynamicSharedMemorySize, S2e);

    // ---- parameter prep ----
    VJobs vj;
    vj.j[0] = {b_n2,  bn2,    30, 32};
    vj.j[1] = {bias2, bias2p, 30, 32};
    vj.j[2] = {attn2, attn2p, 30, 32};
    pad_vec<<<dim3(1, 3), 32>>>(vj);

    WJobs wj;
    wj.j[0]  = {W_n1,  oWn1,  128, 128, 128, 128};
    wj.j[1]  = {W_ni1, oWni1, 128, 128, 128, 128};
    wj.j[2]  = {W_nj1, oWnj1, 128, 128, 128, 128};
    wj.j[3]  = {W_f1,  oWf1,  128, 128, 128, 128};
    wj.j[4]  = {W_n2,  oWn2,  128, 30, 128, 32};
    wj.j[5]  = {W_ni2, oWni2, 128, 30, 128, 32};
    wj.j[6]  = {W_nj2, oWnj2, 128, 30, 128, 32};
    wj.j[7]  = {W_f2,  oWf2,  128, 30, 128, 32};
    wj.j[8]  = {W_ni3, oWni3, 30, 64, 32, 64};
    wj.j[9]  = {W_nj3, oWnj3, 30, 64, 32, 64};
    wj.j[10] = {W_f3,  oWf3,  30, 64, 32, 64};
    conv_wt<<<dim3(64, 11), 256>>>(wj, wtH, wtL);

    // ================= Layer 1 =================
    gemm_pl<128, 128, 64, 32, 0, 1><<<nodeGrid, 256, S1>>>(x, nullptr, wtH + oWni1, wtL + oWni1,
        XNI, nullptr, nullptr, nullptr, nullptr, nullptr, nullptr, nullptr, nullptr, nullptr, Nn);
    gemm_pl<128, 128, 64, 32, 0, 1><<<nodeGrid, 256, S1>>>(x, nullptr, wtH + oWnj1, wtL + oWnj1,
        XNJ, nullptr, nullptr, nullptr, nullptr, nullptr, nullptr, nullptr, nullptr, nullptr, Nn);
    gemm_pl<128, 128, 64, 32, 0, 1><<<nodeGrid, 256, S1>>>(x, nullptr, wtH + oWn1, wtL + oWn1,
        H, nullptr, nullptr, b_n1, nullptr, nullptr, nullptr, nullptr, nullptr, nullptr, Nn);
    gemm_pl<128, 128, 64, 32, 1, 1><<<edgeGrid, 256, S1>>>(e, nullptr, wtH + oWf1, wtL + oWf1,
        nullptr, F1P, F1P + ePN, bias1, XNI, XNJ, src, dst, attn1, score, Ee);

    cudaMemsetAsync(menc, 0x80, (size_t)Nn * sizeof(int), 0);
    cudaMemsetAsync(ssum, 0,    (size_t)Nn * sizeof(float), 0);
    cudaMemsetAsync(X2,   0,    (size_t)Nn * 128 * sizeof(float), 0);
    seg_max<<<perThread, 256>>>(score, dst, menc, Ee);
    seg_expsum<<<perThread, 256>>>(score, dst, menc, ex, ssum, Ee);
    aggregate_k<128><<<((long long)Ee * 32 + 255) / 256, 256>>>(ex, ssum, H, src, dst, X2, Ee);

    // ================= Layer 2 =================
    gemm_pl<32, 128, 16, 32, 0, 1><<<nodeGrid, 256, S2n>>>(X2, nullptr, wtH + oWni2, wtL + oWni2,
        XNI, nullptr, nullptr, nullptr, nullptr, nullptr, nullptr, nullptr, nullptr, nullptr, Nn);
    gemm_pl<32, 128, 16, 32, 0, 1><<<nodeGrid, 256, S2n>>>(X2, nullptr, wtH + oWnj2, wtL + oWnj2,
        XNJ, nullptr, nullptr, nullptr, nullptr, nullptr, nullptr, nullptr, nullptr, nullptr, Nn);
    gemm_pl<32, 128, 16, 32, 0, 1><<<nodeGrid, 256, S2n>>>(X2, nullptr, wtH + oWn2, wtL + oWn2,
        H, nullptr, nullptr, bn2, nullptr, nullptr, nullptr, nullptr, nullptr, nullptr, Nn);
    gemm_pl<32, 128, 16, 32, 1, 0><<<edgeGrid, 256, S2e>>>(F1P, F1P + ePN, wtH + oWf2, wtL + oWf2,
        nullptr, F2P, F2P + F2PN, bias2p, XNI, XNJ, src, dst, attn2p, score, Ee);

    cudaMemsetAsync(menc, 0x80, (size_t)Nn * sizeof(int), 0);
    cudaMemsetAsync(ssum, 0,    (size_t)Nn * sizeof(float), 0);
    cudaMemsetAsync(X3,   0,    (size_t)Nn * 32 * sizeof(float), 0);
    seg_max<<<perThread, 256>>>(score, dst, menc, Ee);
    seg_expsum<<<perThread, 256>>>(score, dst, menc, ex, ssum, Ee);
    aggregate_k<32><<<((long long)Ee * 8 + 255) / 256, 256>>>(ex, ssum, H, src, dst, X3, Ee);

    // ================= Layer 3 (only f) =================
    gemm_pl<64, 32, 32, 32, 0, 1><<<nodeGrid, 256, S3n>>>(X3, nullptr, wtH + oWni3, wtL + oWni3,
        XNI, nullptr, nullptr, nullptr, nullptr, nullptr, nullptr, nullptr, nullptr, nullptr, Nn);
    gemm_pl<64, 32, 32, 32, 0, 1><<<nodeGrid, 256, S3n>>>(X3, nullptr, wtH + oWnj3, wtL + oWnj3,
        XNJ, nullptr, nullptr, nullptr, nullptr, nullptr, nullptr, nullptr, nullptr, nullptr, Nn);
    gemm_pl<64, 32, 32, 32, 2, 0><<<edgeGrid, 256, S3e>>>(F2P, F2P + F2PN, wtH + oWf3, wtL + oWf3,
        out, nullptr, nullptr, bias3, XNI, XNJ, src, dst, nullptr, nullptr, Ee);

    (void)in_sizes; (void)n_in; (void)out_size;
}

// round 12
// speedup vs baseline: 1.4468x; 1.4468x over previous
#include <cuda_runtime.h>
#include <cuda_bf16.h>
#include <cstdint>
#include <cstddef>

#define NN 50000
#define EE 800000

// ---------------- static scratch ----------------
__device__ float g_XNI[(size_t)NN * 128];
__device__ float g_XNJ[(size_t)NN * 128];
__device__ float g_H  [(size_t)NN * 128];
__device__ float g_X2 [(size_t)NN * 128];
__device__ float g_X3 [(size_t)NN * 32];
__device__ float g_score[EE];
__device__ float g_ex[EE];
__device__ int   g_menc[NN];
__device__ float g_ssum[NN];
__device__ float g_bn2[32], g_bias2[32], g_attn2[32];

__device__ __nv_bfloat16 g_F1P[2][(size_t)EE * 128];
__device__ __nv_bfloat16 g_F2P[2][(size_t)EE * 32];
#define WL1 (128 * 128)
#define WL2 (32 * 128)
#define WL3 (64 * 32)
__device__ __nv_bfloat16 g_wts[2][4 * WL1 + 4 * WL2 + 3 * WL3];

// ---------------- helpers ----------------
__device__ __forceinline__ uint32_t pk(float a, float b) {
    __nv_bfloat162 h = __floats2bfloat162_rn(a, b);
    return *(uint32_t*)&h;
}
__device__ __forceinline__ float bfe(float v) {
    return __bfloat162float(__float2bfloat16_rn(v));
}
__device__ __forceinline__ void mma16(float d[4], const uint32_t a[4], const uint32_t b[2]) {
    asm volatile(
        "mma.sync.aligned.m16n8k16.row.col.f32.bf16.bf16.f32 "
        "{%0,%1,%2,%3}, {%4,%5,%6,%7}, {%8,%9}, {%0,%1,%2,%3};\n"
        : "+f"(d[0]), "+f"(d[1]), "+f"(d[2]), "+f"(d[3])
        : "r"(a[0]), "r"(a[1]), "r"(a[2]), "r"(a[3]), "r"(b[0]), "r"(b[1]));
}
__device__ __forceinline__ void ldsm4(uint32_t r[4], uint32_t addr) {
    asm volatile("ldmatrix.sync.aligned.m8n8.x4.shared.b16 {%0,%1,%2,%3}, [%4];"
        : "=r"(r[0]), "=r"(r[1]), "=r"(r[2]), "=r"(r[3]) : "r"(addr));
}
__device__ __forceinline__ void ldsm2(uint32_t r[2], uint32_t addr) {
    asm volatile("ldmatrix.sync.aligned.m8n8.x2.shared.b16 {%0,%1}, [%2];"
        : "=r"(r[0]), "=r"(r[1]) : "r"(addr));
}
__device__ __forceinline__ void cpa16(uint32_t saddr, const void* g) {
    asm volatile("cp.async.ca.shared.global [%0], [%1], 16;" :: "r"(saddr), "l"(g));
}
__device__ __forceinline__ void cp_commit() {
    asm volatile("cp.async.commit_group;");
}
template<int N>
__device__ __forceinline__ void cp_wait() {
    asm volatile("cp.async.wait_group %0;" :: "n"(N) : "memory");
}

// ---------------- weight conversion: f32 [K][N] -> transposed planes [Np][Kp] ----------------
struct WJob { const float* w; int off, K, N, Kp, Np; };
struct WJobs { WJob j[11]; };
__global__ void conv_wt(WJobs js, __nv_bfloat16* hiB, __nv_bfloat16* loB) {
    WJob jb = js.j[blockIdx.y];
    int i = blockIdx.x * blockDim.x + threadIdx.x;
    if (i >= jb.Np * jb.Kp) return;
    int n = i / jb.Kp, k = i % jb.Kp;
    float v = (n < jb.N && k < jb.K) ? jb.w[k * jb.N + n] : 0.0f;
    __nv_bfloat16 h = __float2bfloat16_rn(v);
    hiB[jb.off + i] = h;
    loB[jb.off + i] = __float2bfloat16_rn(v - __bfloat162float(h));
}

struct VJob { const float* in; float* out; int C, nC; };
struct VJobs { VJob j[3]; };
__global__ void pad_vec(VJobs js) {
    VJob p = js.j[blockIdx.y];
    int i = threadIdx.x;
    if (i < p.nC) p.out[i] = (i < p.C) ? p.in[i] : 0.0f;
}

// ---------------- GEMM: B smem-resident, 1 sync per stage, bf16x3 ----------------
// AF32=1: A is f32 [M][K], converted in-kernel (reg staged, double-buffered STS).
// AF32=0: A is bf16 hi/lo planes, 3-stage cp.async ring. M % 128 == 0 for MODE>=1.
// MODE 0: C = A@B (+bias). MODE 1: F planes + score. MODE 2: C = leaky(...).
template<int BN, int KT, int WM, int WN, int MODE, int AF32>
__global__ __launch_bounds__(256, 2) void gemm_pl(
    const void* __restrict__ Apv, const void* __restrict__ Apv2,
    const __nv_bfloat16* __restrict__ Bhi, const __nv_bfloat16* __restrict__ Blo,
    float* __restrict__ C, __nv_bfloat16* __restrict__ Fhi, __nv_bfloat16* __restrict__ Flo,
    const float* __restrict__ bias,
    const float* __restrict__ XNI, const float* __restrict__ XNJ,
    const int* __restrict__ src, const int* __restrict__ dst,
    const float* __restrict__ attn, float* __restrict__ score, int M)
{
    constexpr int BM = 128, T = KT / 16, NS = AF32 ? 2 : 3;
    constexpr int BS = KT * 2 + 16;            // B row stride in bytes (conflict-free)
    constexpr int MT = WM / 16, NT = WN / 8;
    constexpr int WARPS_N = BN / WN;
    static_assert((BM / WM) * (BN / WN) == 8, "need 8 warps");

    extern __shared__ __align__(16) char dynsm[];
    char* sBp = dynsm + NS * 2 * BM * 48;
    float* s_sc = (float*)(sBp + 2 * BN * BS);

    const int tid  = threadIdx.x;
    const int warp = tid >> 5, lane = tid & 31;
    const int gid  = lane >> 2, tig = lane & 3;
    const int wm   = warp / WARPS_N, wn = warp % WARPS_N;
    const int rowW = wm * WM, colW = wn * WN;
    const int row0 = blockIdx.x * BM;

    const uint32_t aBase = (uint32_t)__cvta_generic_to_shared(dynsm);
    const uint32_t bBase = (uint32_t)__cvta_generic_to_shared(sBp);

    const float* Af = (const float*)Apv;
    const __nv_bfloat16* Ahi = (const __nv_bfloat16*)Apv;
    const __nv_bfloat16* Alo = (const __nv_bfloat16*)Apv2;

    if (MODE == 1 && tid < BM) s_sc[tid] = 0.0f;

    float acc[MT][NT][4];
    #pragma unroll
    for (int i = 0; i < MT; i++)
        #pragma unroll
        for (int j = 0; j < NT; j++)
            #pragma unroll
            for (int t = 0; t < 4; t++) acc[i][j][t] = 0.0f;

    const int lrA = lane & 15;
    const int kofA = ((lane >> 4) & 1) * 16;
    const int lrB = lane & 7;
    const int kofB = ((lane >> 3) & 1) * 16;

    const int arow = tid >> 1, ahalf = tid & 1;
    float areg[8];

    auto issueB = [&]() {
        constexpr int CH = KT / 8;             // 16B chunks per row
        #pragma unroll
        for (int c = tid; c < 2 * BN * CH; c += 256) {
            int pl = c / (BN * CH);
            int rem = c - pl * BN * CH;
            int n = rem / CH, ch = rem - n * CH;
            const __nv_bfloat16* g = (pl ? Blo : Bhi) + (size_t)n * KT + ch * 8;
            cpa16(bBase + (uint32_t)((pl * BN + n) * BS + ch * 16), g);
        }
    };
    auto loadAf32 = [&](int t) {
        int gr = row0 + arow;
        if (gr < M) {
            const float* p = &Af[(size_t)gr * KT + t * 16 + ahalf * 8];
            float4 q0 = *(const float4*)p;
            float4 q1 = *(const float4*)(p + 4);
            areg[0] = q0.x; areg[1] = q0.y; areg[2] = q0.z; areg[3] = q0.w;
            areg[4] = q1.x; areg[5] = q1.y; areg[6] = q1.z; areg[7] = q1.w;
        } else {
            #pragma unroll
            for (int u = 0; u < 8; u++) areg[u] = 0.0f;
        }
    };
    auto stsA = [&](int s) {
        __nv_bfloat16 h[8], l[8];
        #pragma unroll
        for (int u = 0; u < 8; u++) {
            h[u] = __float2bfloat16_rn(areg[u]);
            l[u] = __float2bfloat16_rn(areg[u] - __bfloat162float(h[u]));
        }
        __nv_bfloat16* base = (__nv_bfloat16*)dynsm;
        *(uint4*)&base[((s * 2 + 0) * BM + arow) * 24 + ahalf * 8] = *(uint4*)h;
        *(uint4*)&base[((s * 2 + 1) * BM + arow) * 24 + ahalf * 8] = *(uint4*)l;
    };
    auto issueApl = [&](int t, int s) {
        #pragma unroll
        for (int c = tid; c < BM * 4; c += 256) {
            int half = c & 1, pl = (c >> 1) & 1, r = c >> 2;
            const __nv_bfloat16* g = (pl ? Alo : Ahi) + (size_t)(row0 + r) * KT + t * 16 + half * 8;
            cpa16(aBase + (uint32_t)(((s * 2 + pl) * BM + r) * 48 + half * 16), g);
        }
    };
    auto mmaStage = [&](int s, int t) {
        uint32_t ah[MT][4], al[MT][4];
        uint32_t aOff = aBase + (uint32_t)(s * 2 * BM * 48);
        #pragma unroll
        for (int i = 0; i < MT; i++) {
            uint32_t ra = aOff + (uint32_t)((rowW + i * 16 + lrA) * 48) + kofA;
            ldsm4(ah[i], ra);
            ldsm4(al[i], ra + (uint32_t)(BM * 48));
        }
        #pragma unroll
        for (int j = 0; j < NT; j++) {
            uint32_t rb = bBase + (uint32_t)((colW + j * 8 + lrB) * BS) + (uint32_t)(t * 32) + kofB;
            uint32_t bh[2], bl[2];
            ldsm2(bh, rb);
            ldsm2(bl, rb + (uint32_t)(BN * BS));
            // term-major: each acc touched once per sub-loop -> RAW spacing = MT
            #pragma unroll
            for (int i = 0; i < MT; i++)
                mma16(acc[i][j], ah[i], bh);
            #pragma unroll
            for (int i = 0; i < MT; i++)
                mma16(acc[i][j], ah[i], bl);
            #pragma unroll
            for (int i = 0; i < MT; i++)
                mma16(acc[i][j], al[i], bh);
        }
    };

    if (AF32) {
        loadAf32(0);
        issueB(); cp_commit();
        stsA(0);
        cp_wait<0>();
        __syncthreads();
        for (int t = 0; t < T; t++) {
            int s = t & 1;
            if (t + 1 < T) loadAf32(t + 1);
            mmaStage(s, t);
            if (t + 1 < T) stsA(1 - s);
            __syncthreads();
        }
    } else {
        issueB(); issueApl(0, 0); cp_commit();
        if (T > 1) { issueApl(1, 1); cp_commit(); }
        for (int t = 0; t < T; t++) {
            if (t < T - 1) cp_wait<1>(); else cp_wait<0>();
            __syncthreads();
            mmaStage(t % 3, t);
            if (t + 2 < T) { issueApl(t + 2, (t + 2) % 3); cp_commit(); }
        }
    }

    // ---------------- epilogue ----------------
    if (MODE == 0) {
        #pragma unroll
        for (int i = 0; i < MT; i++) {
            int gr1 = row0 + rowW + i * 16 + gid;
            int gr2 = gr1 + 8;
            #pragma unroll
            for (int j = 0; j < NT; j++) {
                int c = colW + j * 8 + 2 * tig;
                float b0 = bias ? bias[c] : 0.0f;
                float b1 = bias ? bias[c + 1] : 0.0f;
                if (gr1 < M)
                    *(float2*)&C[(size_t)gr1 * BN + c] =
                        make_float2(acc[i][j][0] + b0, acc[i][j][1] + b1);
                if (gr2 < M)
                    *(float2*)&C[(size_t)gr2 * BN + c] =
                        make_float2(acc[i][j][2] + b0, acc[i][j][3] + b1);
            }
        }
    } else {
        #pragma unroll
        for (int i = 0; i < MT; i++) {
            int lr1 = rowW + i * 16 + gid, lr2 = lr1 + 8;
            int gr1 = row0 + lr1, gr2 = row0 + lr2;
            int sn1 = src[gr1], dn1 = dst[gr1];
            int sn2 = src[gr2], dn2 = dst[gr2];
            float sc1 = 0.0f, sc2 = 0.0f;
            #pragma unroll
            for (int j = 0; j < NT; j++) {
                int c = colW + j * 8 + 2 * tig;
                float b0 = bias[c], b1 = bias[c + 1];
                float2 xi1 = *(const float2*)&XNI[(size_t)sn1 * BN + c];
                float2 xj1 = *(const float2*)&XNJ[(size_t)dn1 * BN + c];
                float o0 = acc[i][j][0] + xi1.x + xj1.x + b0;
                float o1 = acc[i][j][1] + xi1.y + xj1.y + b1;
                o0 = o0 > 0.f ? o0 : 0.01f * o0;
                o1 = o1 > 0.f ? o1 : 0.01f * o1;
                float2 xi2 = *(const float2*)&XNI[(size_t)sn2 * BN + c];
                float2 xj2 = *(const float2*)&XNJ[(size_t)dn2 * BN + c];
                float p0 = acc[i][j][2] + xi2.x + xj2.x + b0;
                float p1 = acc[i][j][3] + xi2.y + xj2.y + b1;
                p0 = p0 > 0.f ? p0 : 0.01f * p0;
                p1 = p1 > 0.f ? p1 : 0.01f * p1;
                if (MODE == 1) {
                    *(uint32_t*)&Fhi[(size_t)gr1 * BN + c] = pk(o0, o1);
                    *(uint32_t*)&Flo[(size_t)gr1 * BN + c] = pk(o0 - bfe(o0), o1 - bfe(o1));
                    *(uint32_t*)&Fhi[(size_t)gr2 * BN + c] = pk(p0, p1);
                    *(uint32_t*)&Flo[(size_t)gr2 * BN + c] = pk(p0 - bfe(p0), p1 - bfe(p1));
                    float a0 = attn[c], a1 = attn[c + 1];
                    sc1 += o0 * a0 + o1 * a1;
                    sc2 += p0 * a0 + p1 * a1;
                } else {
                    *(float2*)&C[(size_t)gr1 * BN + c] = make_float2(o0, o1);
                    *(float2*)&C[(size_t)gr2 * BN + c] = make_float2(p0, p1);
                }
            }
            if (MODE == 1) {
                sc1 += __shfl_xor_sync(0xffffffffu, sc1, 1);
                sc1 += __shfl_xor_sync(0xffffffffu, sc1, 2);
                sc2 += __shfl_xor_sync(0xffffffffu, sc2, 1);
                sc2 += __shfl_xor_sync(0xffffffffu, sc2, 2);
                if (tig == 0) {
                    atomicAdd(&s_sc[lr1], sc1);
                    atomicAdd(&s_sc[lr2], sc2);
                }
            }
        }
        if (MODE == 1) {
            __syncthreads();
            if (tid < BM) score[row0 + tid] = s_sc[tid];
        }
    }
}

// ---------------- segment softmax over dst ----------------
__device__ __forceinline__ int enc_f(float f) {
    int i = __float_as_int(f);
    return i >= 0 ? i : (i ^ 0x7fffffff);
}
__device__ __forceinline__ float dec_f(int i) {
    return __int_as_float(i >= 0 ? i : (i ^ 0x7fffffff));
}

__global__ void seg_max(const float* __restrict__ score, const int* __restrict__ dst,
                        int* __restrict__ menc, int E) {
    int e = blockIdx.x * blockDim.x + threadIdx.x;
    if (e >= E) return;
    atomicMax(&menc[dst[e]], enc_f(score[e]));
}

__global__ void seg_expsum(const float* __restrict__ score, const int* __restrict__ dst,
                           const int* __restrict__ menc, float* __restrict__ ex,
                           float* __restrict__ ssum, int E) {
    int e = blockIdx.x * blockDim.x + threadIdx.x;
    if (e >= E) return;
    int d = dst[e];
    float ev = expf(score[e] - dec_f(menc[d]));
    ex[e] = ev;
    atomicAdd(&ssum[d], ev);
}

template<int DO>
__global__ void aggregate_k(const float* __restrict__ ex, const float* __restrict__ ssum,
                            const float* __restrict__ H, const int* __restrict__ src,
                            const int* __restrict__ dst, float* __restrict__ out, int E) {
    constexpr int L = DO / 4;
    long long gt = (long long)blockIdx.x * blockDim.x + threadIdx.x;
    int e = (int)(gt / L), l = (int)(gt % L);
    if (e >= E) return;
    int dn = dst[e];
    float a = ex[e] / ssum[dn];
    float4 h = *(const float4*)&H[(size_t)src[e] * DO + l * 4];
    float* p = &out[(size_t)dn * DO + l * 4];
    asm volatile("red.global.add.v4.f32 [%0], {%1,%2,%3,%4};"
                 :: "l"(p), "f"(h.x * a), "f"(h.y * a), "f"(h.z * a), "f"(h.w * a)
                 : "memory");
}

// ---------------- host ----------------
static inline constexpr int smemSz(int BN, int KT, int AF32) {
    return (AF32 ? 2 : 3) * 2 * 128 * 48 + 2 * BN * (KT * 2 + 16) + 512;
}

extern "C" void kernel_launch(void* const* d_in, const int* in_sizes, int n_in,
                              void* d_out, int out_size) {
    const float* x    = (const float*)d_in[0];
    const float* e    = (const float*)d_in[1];
    const int*   src  = (const int*)d_in[2];
    const int*   dst  = (const int*)d_in[3];

    const float* W_n1  = (const float*)d_in[4];
    const float* b_n1  = (const float*)d_in[5];
    const float* W_ni1 = (const float*)d_in[6];
    const float* W_nj1 = (const float*)d_in[7];
    const float* W_f1  = (const float*)d_in[8];
    const float* attn1 = (const float*)d_in[9];
    const float* bias1 = (const float*)d_in[10];

    const float* W_n2  = (const float*)d_in[11];
    const float* b_n2  = (const float*)d_in[12];
    const float* W_ni2 = (const float*)d_in[13];
    const float* W_nj2 = (const float*)d_in[14];
    const float* W_f2  = (const float*)d_in[15];
    const float* attn2 = (const float*)d_in[16];
    const float* bias2 = (const float*)d_in[17];

    const float* W_ni3 = (const float*)d_in[20];
    const float* W_nj3 = (const float*)d_in[21];
    const float* W_f3  = (const float*)d_in[22];
    const float* bias3 = (const float*)d_in[24];

    float* out = (float*)d_out;

    float *XNI, *XNJ, *H, *X2, *X3, *score, *ex, *ssum, *bn2, *bias2p, *attn2p;
    int* menc;
    __nv_bfloat16 *F1P, *F2P, *wts;
    cudaGetSymbolAddress((void**)&XNI, g_XNI);
    cudaGetSymbolAddress((void**)&XNJ, g_XNJ);
    cudaGetSymbolAddress((void**)&H,   g_H);
    cudaGetSymbolAddress((void**)&X2,  g_X2);
    cudaGetSymbolAddress((void**)&X3,  g_X3);
    cudaGetSymbolAddress((void**)&score, g_score);
    cudaGetSymbolAddress((void**)&ex,  g_ex);
    cudaGetSymbolAddress((void**)&ssum, g_ssum);
    cudaGetSymbolAddress((void**)&menc, g_menc);
    cudaGetSymbolAddress((void**)&bn2,  g_bn2);
    cudaGetSymbolAddress((void**)&bias2p, g_bias2);
    cudaGetSymbolAddress((void**)&attn2p, g_attn2);
    cudaGetSymbolAddress((void**)&F1P, g_F1P);
    cudaGetSymbolAddress((void**)&F2P, g_F2P);
    cudaGetSymbolAddress((void**)&wts, g_wts);

    const size_t ePN  = (size_t)EE * 128;
    const size_t F2PN = (size_t)EE * 32;
    const size_t WTN  = 4 * WL1 + 4 * WL2 + 3 * WL3;
    __nv_bfloat16 *wtH = wts, *wtL = wts + WTN;
    const int oWn1 = 0 * WL1, oWni1 = 1 * WL1, oWnj1 = 2 * WL1, oWf1 = 3 * WL1;
    const int base2 = 4 * WL1;
    const int oWn2 = base2, oWni2 = base2 + WL2, oWnj2 = base2 + 2 * WL2, oWf2 = base2 + 3 * WL2;
    const int base3 = base2 + 4 * WL2;
    const int oWni3 = base3, oWnj3 = base3 + WL3, oWf3 = base3 + 2 * WL3;

    const int Nn = NN, Ee = EE;
    const int nodeGrid = (Nn + 127) / 128;
    const int edgeGrid = Ee / 128;
    const int perThread = (Ee + 255) / 256;

    constexpr int S1  = smemSz(128, 128, 1);
    constexpr int S2n = smemSz(32, 128, 1);
    constexpr int S2e = smemSz(32, 128, 0);
    constexpr int S3n = smemSz(64, 32, 1);
    constexpr int S3e = smemSz(64, 32, 0);
    cudaFuncSetAttribute(gemm_pl<128, 128, 64, 32, 0, 1>, cudaFuncAttributeMaxDynamicSharedMemorySize, S1);
    cudaFuncSetAttribute(gemm_pl<128, 128, 64, 32, 1, 1>, cudaFuncAttributeMaxDynamicSharedMemorySize, S1);
    cudaFuncSetAttribute(gemm_pl<32, 128, 16, 32, 1, 0>, cudaFuncAttributeMaxDynamicSharedMemorySize, S2e);

    // ---- parameter prep ----
    VJobs vj;
    vj.j[0] = {b_n2,  bn2,    30, 32};
    vj.j[1] = {bias2, bias2p, 30, 32};
    vj.j[2] = {attn2, attn2p, 30, 32};
    pad_vec<<<dim3(1, 3), 32>>>(vj);

    WJobs wj;
    wj.j[0]  = {W_n1,  oWn1,  128, 128, 128, 128};
    wj.j[1]  = {W_ni1, oWni1, 128, 128, 128, 128};
    wj.j[2]  = {W_nj1, oWnj1, 128, 128, 128, 128};
    wj.j[3]  = {W_f1,  oWf1,  128, 128, 128, 128};
    wj.j[4]  = {W_n2,  oWn2,  128, 30, 128, 32};
    wj.j[5]  = {W_ni2, oWni2, 128, 30, 128, 32};
    wj.j[6]  = {W_nj2, oWnj2, 128, 30, 128, 32};
    wj.j[7]  = {W_f2,  oWf2,  128, 30, 128, 32};
    wj.j[8]  = {W_ni3, oWni3, 30, 64, 32, 64};
    wj.j[9]  = {W_nj3, oWnj3, 30, 64, 32, 64};
    wj.j[10] = {W_f3,  oWf3,  30, 64, 32, 64};
    conv_wt<<<dim3(64, 11), 256>>>(wj, wtH, wtL);

    // ================= Layer 1 =================
    gemm_pl<128, 128, 64, 32, 0, 1><<<nodeGrid, 256, S1>>>(x, nullptr, wtH + oWni1, wtL + oWni1,
        XNI, nullptr, nullptr, nullptr, nullptr, nullptr, nullptr, nullptr, nullptr, nullptr, Nn);
    gemm_pl<128, 128, 64, 32, 0, 1><<<nodeGrid, 256, S1>>>(x, nullptr, wtH + oWnj1, wtL + oWnj1,
        XNJ, nullptr, nullptr, nullptr, nullptr, nullptr, nullptr, nullptr, nullptr, nullptr, Nn);
    gemm_pl<128, 128, 64, 32, 0, 1><<<nodeGrid, 256, S1>>>(x, nullptr, wtH + oWn1, wtL + oWn1,
        H, nullptr, nullptr, b_n1, nullptr, nullptr, nullptr, nullptr, nullptr, nullptr, Nn);
    gemm_pl<128, 128, 64, 32, 1, 1><<<edgeGrid, 256, S1>>>(e, nullptr, wtH + oWf1, wtL + oWf1,
        nullptr, F1P, F1P + ePN, bias1, XNI, XNJ, src, dst, attn1, score, Ee);

    cudaMemsetAsync(menc, 0x80, (size_t)Nn * sizeof(int), 0);
    cudaMemsetAsync(ssum, 0,    (size_t)Nn * sizeof(float), 0);
    cudaMemsetAsync(X2,   0,    (size_t)Nn * 128 * sizeof(float), 0);
    seg_max<<<perThread, 256>>>(score, dst, menc, Ee);
    seg_expsum<<<perThread, 256>>>(score, dst, menc, ex, ssum, Ee);
    aggregate_k<128><<<((long long)Ee * 32 + 255) / 256, 256>>>(ex, ssum, H, src, dst, X2, Ee);

    // ================= Layer 2 =================
    gemm_pl<32, 128, 16, 32, 0, 1><<<nodeGrid, 256, S2n>>>(X2, nullptr, wtH + oWni2, wtL + oWni2,
        XNI, nullptr, nullptr, nullptr, nullptr, nullptr, nullptr, nullptr, nullptr, nullptr, Nn);
    gemm_pl<32, 128, 16, 32, 0, 1><<<nodeGrid, 256, S2n>>>(X2, nullptr, wtH + oWnj2, wtL + oWnj2,
        XNJ, nullptr, nullptr, nullptr, nullptr, nullptr, nullptr, nullptr, nullptr, nullptr, Nn);
    gemm_pl<32, 128, 16, 32, 0, 1><<<nodeGrid, 256, S2n>>>(X2, nullptr, wtH + oWn2, wtL + oWn2,
        H, nullptr, nullptr, bn2, nullptr, nullptr, nullptr, nullptr, nullptr, nullptr, Nn);
    gemm_pl<32, 128, 16, 32, 1, 0><<<edgeGrid, 256, S2e>>>(F1P, F1P + ePN, wtH + oWf2, wtL + oWf2,
        nullptr, F2P, F2P + F2PN, bias2p, XNI, XNJ, src, dst, attn2p, score, Ee);

    cudaMemsetAsync(menc, 0x80, (size_t)Nn * sizeof(int), 0);
    cudaMemsetAsync(ssum, 0,    (size_t)Nn * sizeof(float), 0);
    cudaMemsetAsync(X3,   0,    (size_t)Nn * 32 * sizeof(float), 0);
    seg_max<<<perThread, 256>>>(score, dst, menc, Ee);
    seg_expsum<<<perThread, 256>>>(score, dst, menc, ex, ssum, Ee);
    aggregate_k<32><<<((long long)Ee * 8 + 255) / 256, 256>>>(ex, ssum, H, src, dst, X3, Ee);

    // ================= Layer 3 (only f) =================
    gemm_pl<64, 32, 32, 32, 0, 1><<<nodeGrid, 256, S3n>>>(X3, nullptr, wtH + oWni3, wtL + oWni3,
        XNI, nullptr, nullptr, nullptr, nullptr, nullptr, nullptr, nullptr, nullptr, nullptr, Nn);
    gemm_pl<64, 32, 32, 32, 0, 1><<<nodeGrid, 256, S3n>>>(X3, nullptr, wtH + oWnj3, wtL + oWnj3,
        XNJ, nullptr, nullptr, nullptr, nullptr, nullptr, nullptr, nullptr, nullptr, nullptr, Nn);
    gemm_pl<64, 32, 32, 32, 2, 0><<<edgeGrid, 256, S3e>>>(F2P, F2P + F2PN, wtH + oWf3, wtL + oWf3,
        out, nullptr, nullptr, bias3, XNI, XNJ, src, dst, nullptr, nullptr, Ee);

    (void)in_sizes; (void)n_in; (void)out_size;
}

// round 13
// speedup vs baseline: 1.4595x; 1.0088x over previous
#include <cuda_runtime.h>
#include <cuda_bf16.h>
#include <cstdint>
#include <cstddef>

#define NN 50000
#define EE 800000

// ---------------- static scratch ----------------
__device__ float g_XNI[(size_t)NN * 128];
__device__ float g_XNJ[(size_t)NN * 128];
__device__ float g_H  [(size_t)NN * 128];
__device__ float g_X2 [(size_t)NN * 128];
__device__ float g_X3 [(size_t)NN * 32];
__device__ float g_ex[EE];
__device__ float g_ssum[NN];
__device__ float g_bn2[32], g_bias2[32], g_attn2[32];

__device__ __nv_bfloat16 g_F1P[2][(size_t)EE * 128];
__device__ __nv_bfloat16 g_F2P[2][(size_t)EE * 32];
#define WL1 (128 * 128)
#define WL2 (32 * 128)
#define WL3 (64 * 32)
__device__ __nv_bfloat16 g_wts[2][4 * WL1 + 4 * WL2 + 3 * WL3];

// ---------------- helpers ----------------
__device__ __forceinline__ uint32_t pk(float a, float b) {
    __nv_bfloat162 h = __floats2bfloat162_rn(a, b);
    return *(uint32_t*)&h;
}
__device__ __forceinline__ float bfe(float v) {
    return __bfloat162float(__float2bfloat16_rn(v));
}
__device__ __forceinline__ void mma16(float d[4], const uint32_t a[4], const uint32_t b[2]) {
    asm volatile(
        "mma.sync.aligned.m16n8k16.row.col.f32.bf16.bf16.f32 "
        "{%0,%1,%2,%3}, {%4,%5,%6,%7}, {%8,%9}, {%0,%1,%2,%3};\n"
        : "+f"(d[0]), "+f"(d[1]), "+f"(d[2]), "+f"(d[3])
        : "r"(a[0]), "r"(a[1]), "r"(a[2]), "r"(a[3]), "r"(b[0]), "r"(b[1]));
}
__device__ __forceinline__ void ldsm4(uint32_t r[4], uint32_t addr) {
    asm volatile("ldmatrix.sync.aligned.m8n8.x4.shared.b16 {%0,%1,%2,%3}, [%4];"
        : "=r"(r[0]), "=r"(r[1]), "=r"(r[2]), "=r"(r[3]) : "r"(addr));
}
__device__ __forceinline__ void ldsm2(uint32_t r[2], uint32_t addr) {
    asm volatile("ldmatrix.sync.aligned.m8n8.x2.shared.b16 {%0,%1}, [%2];"
        : "=r"(r[0]), "=r"(r[1]) : "r"(addr));
}
__device__ __forceinline__ void cpa16(uint32_t saddr, const void* g) {
    asm volatile("cp.async.ca.shared.global [%0], [%1], 16;" :: "r"(saddr), "l"(g));
}
__device__ __forceinline__ void cp_commit() {
    asm volatile("cp.async.commit_group;");
}
template<int N>
__device__ __forceinline__ void cp_wait() {
    asm volatile("cp.async.wait_group %0;" :: "n"(N) : "memory");
}

// ---------------- weight conversion: f32 [K][N] -> transposed planes [Np][Kp] ----------------
struct WJob { const float* w; int off, K, N, Kp, Np; };
struct WJobs { WJob j[11]; };
__global__ void conv_wt(WJobs js, __nv_bfloat16* hiB, __nv_bfloat16* loB) {
    WJob jb = js.j[blockIdx.y];
    int i = blockIdx.x * blockDim.x + threadIdx.x;
    if (i >= jb.Np * jb.Kp) return;
    int n = i / jb.Kp, k = i % jb.Kp;
    float v = (n < jb.N && k < jb.K) ? jb.w[k * jb.N + n] : 0.0f;
    __nv_bfloat16 h = __float2bfloat16_rn(v);
    hiB[jb.off + i] = h;
    loB[jb.off + i] = __float2bfloat16_rn(v - __bfloat162float(h));
}

struct VJob { const float* in; float* out; int C, nC; };
struct VJobs { VJob j[3]; };
__global__ void pad_vec(VJobs js) {
    VJob p = js.j[blockIdx.y];
    int i = threadIdx.x;
    if (i < p.nC) p.out[i] = (i < p.C) ? p.in[i] : 0.0f;
}

// ---------------- GEMM: B smem-resident, 1 sync per stage, bf16x3 ----------------
// AF32=1: A is f32 [M][K], converted in-kernel. AF32=0: A is bf16 hi/lo planes.
// MODE 0: C = A@B (+bias).
// MODE 1: F planes = split(leaky(A@B + XNI[src] + XNJ[dst] + bias));
//         fused softmax numerator: ex[edge] = exp(score); atomicAdd(ssum[dst], ex)
// MODE 2: C = leaky(...) (no score). MODE>=1: M % 128 == 0.
template<int BN, int KT, int WM, int WN, int MODE, int AF32>
__global__ __launch_bounds__(256, 2) void gemm_pl(
    const void* __restrict__ Apv, const void* __restrict__ Apv2,
    const __nv_bfloat16* __restrict__ Bhi, const __nv_bfloat16* __restrict__ Blo,
    float* __restrict__ C, __nv_bfloat16* __restrict__ Fhi, __nv_bfloat16* __restrict__ Flo,
    const float* __restrict__ bias,
    const float* __restrict__ XNI, const float* __restrict__ XNJ,
    const int* __restrict__ src, const int* __restrict__ dst,
    const float* __restrict__ attn, float* __restrict__ ex, float* __restrict__ ssum,
    int M)
{
    constexpr int BM = 128, T = KT / 16, NS = AF32 ? 2 : 3;
    constexpr int BS = KT * 2 + 16;            // B row stride in bytes (conflict-free)
    constexpr int MT = WM / 16, NT = WN / 8;
    constexpr int WARPS_N = BN / WN;
    static_assert((BM / WM) * (BN / WN) == 8, "need 8 warps");

    extern __shared__ __align__(16) char dynsm[];
    char* sBp = dynsm + NS * 2 * BM * 48;
    float* s_sc = (float*)(sBp + 2 * BN * BS);

    const int tid  = threadIdx.x;
    const int warp = tid >> 5, lane = tid & 31;
    const int gid  = lane >> 2, tig = lane & 3;
    const int wm   = warp / WARPS_N, wn = warp % WARPS_N;
    const int rowW = wm * WM, colW = wn * WN;
    const int row0 = blockIdx.x * BM;

    const uint32_t aBase = (uint32_t)__cvta_generic_to_shared(dynsm);
    const uint32_t bBase = (uint32_t)__cvta_generic_to_shared(sBp);

    const float* Af = (const float*)Apv;
    const __nv_bfloat16* Ahi = (const __nv_bfloat16*)Apv;
    const __nv_bfloat16* Alo = (const __nv_bfloat16*)Apv2;

    if (MODE == 1 && tid < BM) s_sc[tid] = 0.0f;

    float acc[MT][NT][4];
    #pragma unroll
    for (int i = 0; i < MT; i++)
        #pragma unroll
        for (int j = 0; j < NT; j++)
            #pragma unroll
            for (int t = 0; t < 4; t++) acc[i][j][t] = 0.0f;

    const int lrA = lane & 15;
    const int kofA = ((lane >> 4) & 1) * 16;
    const int lrB = lane & 7;
    const int kofB = ((lane >> 3) & 1) * 16;

    const int arow = tid >> 1, ahalf = tid & 1;
    float areg[8];

    auto issueB = [&]() {
        constexpr int CH = KT / 8;             // 16B chunks per row
        #pragma unroll
        for (int c = tid; c < 2 * BN * CH; c += 256) {
            int pl = c / (BN * CH);
            int rem = c - pl * BN * CH;
            int n = rem / CH, ch = rem - n * CH;
            const __nv_bfloat16* g = (pl ? Blo : Bhi) + (size_t)n * KT + ch * 8;
            cpa16(bBase + (uint32_t)((pl * BN + n) * BS + ch * 16), g);
        }
    };
    auto loadAf32 = [&](int t) {
        int gr = row0 + arow;
        if (gr < M) {
            const float* p = &Af[(size_t)gr * KT + t * 16 + ahalf * 8];
            float4 q0 = *(const float4*)p;
            float4 q1 = *(const float4*)(p + 4);
            areg[0] = q0.x; areg[1] = q0.y; areg[2] = q0.z; areg[3] = q0.w;
            areg[4] = q1.x; areg[5] = q1.y; areg[6] = q1.z; areg[7] = q1.w;
        } else {
            #pragma unroll
            for (int u = 0; u < 8; u++) areg[u] = 0.0f;
        }
    };
    auto stsA = [&](int s) {
        __nv_bfloat16 h[8], l[8];
        #pragma unroll
        for (int u = 0; u < 8; u++) {
            h[u] = __float2bfloat16_rn(areg[u]);
            l[u] = __float2bfloat16_rn(areg[u] - __bfloat162float(h[u]));
        }
        __nv_bfloat16* base = (__nv_bfloat16*)dynsm;
        *(uint4*)&base[((s * 2 + 0) * BM + arow) * 24 + ahalf * 8] = *(uint4*)h;
        *(uint4*)&base[((s * 2 + 1) * BM + arow) * 24 + ahalf * 8] = *(uint4*)l;
    };
    auto issueApl = [&](int t, int s) {
        #pragma unroll
        for (int c = tid; c < BM * 4; c += 256) {
            int half = c & 1, pl = (c >> 1) & 1, r = c >> 2;
            const __nv_bfloat16* g = (pl ? Alo : Ahi) + (size_t)(row0 + r) * KT + t * 16 + half * 8;
            cpa16(aBase + (uint32_t)(((s * 2 + pl) * BM + r) * 48 + half * 16), g);
        }
    };
    auto mmaStage = [&](int s, int t) {
        uint32_t ah[MT][4], al[MT][4];
        uint32_t aOff = aBase + (uint32_t)(s * 2 * BM * 48);
        #pragma unroll
        for (int i = 0; i < MT; i++) {
            uint32_t ra = aOff + (uint32_t)((rowW + i * 16 + lrA) * 48) + kofA;
            ldsm4(ah[i], ra);
            ldsm4(al[i], ra + (uint32_t)(BM * 48));
        }
        #pragma unroll
        for (int j = 0; j < NT; j++) {
            uint32_t rb = bBase + (uint32_t)((colW + j * 8 + lrB) * BS) + (uint32_t)(t * 32) + kofB;
            uint32_t bh[2], bl[2];
            ldsm2(bh, rb);
            ldsm2(bl, rb + (uint32_t)(BN * BS));
            #pragma unroll
            for (int i = 0; i < MT; i++)
                mma16(acc[i][j], ah[i], bh);
            #pragma unroll
            for (int i = 0; i < MT; i++)
                mma16(acc[i][j], ah[i], bl);
            #pragma unroll
            for (int i = 0; i < MT; i++)
                mma16(acc[i][j], al[i], bh);
        }
    };

    if (AF32) {
        loadAf32(0);
        issueB(); cp_commit();
        stsA(0);
        cp_wait<0>();
        __syncthreads();
        for (int t = 0; t < T; t++) {
            int s = t & 1;
            if (t + 1 < T) loadAf32(t + 1);
            mmaStage(s, t);
            if (t + 1 < T) stsA(1 - s);
            __syncthreads();
        }
    } else {
        issueB(); issueApl(0, 0); cp_commit();
        if (T > 1) { issueApl(1, 1); cp_commit(); }
        for (int t = 0; t < T; t++) {
            if (t < T - 1) cp_wait<1>(); else cp_wait<0>();
            __syncthreads();
            mmaStage(t % 3, t);
            if (t + 2 < T) { issueApl(t + 2, (t + 2) % 3); cp_commit(); }
        }
    }

    // ---------------- epilogue ----------------
    if (MODE == 0) {
        #pragma unroll
        for (int i = 0; i < MT; i++) {
            int gr1 = row0 + rowW + i * 16 + gid;
            int gr2 = gr1 + 8;
            #pragma unroll
            for (int j = 0; j < NT; j++) {
                int c = colW + j * 8 + 2 * tig;
                float b0 = bias ? bias[c] : 0.0f;
                float b1 = bias ? bias[c + 1] : 0.0f;
                if (gr1 < M)
                    *(float2*)&C[(size_t)gr1 * BN + c] =
                        make_float2(acc[i][j][0] + b0, acc[i][j][1] + b1);
                if (gr2 < M)
                    *(float2*)&C[(size_t)gr2 * BN + c] =
                        make_float2(acc[i][j][2] + b0, acc[i][j][3] + b1);
            }
        }
    } else {
        #pragma unroll
        for (int i = 0; i < MT; i++) {
            int lr1 = rowW + i * 16 + gid, lr2 = lr1 + 8;
            int gr1 = row0 + lr1, gr2 = row0 + lr2;
            int sn1 = src[gr1], dn1 = dst[gr1];
            int sn2 = src[gr2], dn2 = dst[gr2];
            float sc1 = 0.0f, sc2 = 0.0f;
            #pragma unroll
            for (int j = 0; j < NT; j++) {
                int c = colW + j * 8 + 2 * tig;
                float b0 = bias[c], b1 = bias[c + 1];
                float2 xi1 = *(const float2*)&XNI[(size_t)sn1 * BN + c];
                float2 xj1 = *(const float2*)&XNJ[(size_t)dn1 * BN + c];
                float o0 = acc[i][j][0] + xi1.x + xj1.x + b0;
                float o1 = acc[i][j][1] + xi1.y + xj1.y + b1;
                o0 = o0 > 0.f ? o0 : 0.01f * o0;
                o1 = o1 > 0.f ? o1 : 0.01f * o1;
                float2 xi2 = *(const float2*)&XNI[(size_t)sn2 * BN + c];
                float2 xj2 = *(const float2*)&XNJ[(size_t)dn2 * BN + c];
                float p0 = acc[i][j][2] + xi2.x + xj2.x + b0;
                float p1 = acc[i][j][3] + xi2.y + xj2.y + b1;
                p0 = p0 > 0.f ? p0 : 0.01f * p0;
                p1 = p1 > 0.f ? p1 : 0.01f * p1;
                if (MODE == 1) {
                    *(uint32_t*)&Fhi[(size_t)gr1 * BN + c] = pk(o0, o1);
                    *(uint32_t*)&Flo[(size_t)gr1 * BN + c] = pk(o0 - bfe(o0), o1 - bfe(o1));
                    *(uint32_t*)&Fhi[(size_t)gr2 * BN + c] = pk(p0, p1);
                    *(uint32_t*)&Flo[(size_t)gr2 * BN + c] = pk(p0 - bfe(p0), p1 - bfe(p1));
                    float a0 = attn[c], a1 = attn[c + 1];
                    sc1 += o0 * a0 + o1 * a1;
                    sc2 += p0 * a0 + p1 * a1;
                } else {
                    *(float2*)&C[(size_t)gr1 * BN + c] = make_float2(o0, o1);
                    *(float2*)&C[(size_t)gr2 * BN + c] = make_float2(p0, p1);
                }
            }
            if (MODE == 1) {
                sc1 += __shfl_xor_sync(0xffffffffu, sc1, 1);
                sc1 += __shfl_xor_sync(0xffffffffu, sc1, 2);
                sc2 += __shfl_xor_sync(0xffffffffu, sc2, 1);
                sc2 += __shfl_xor_sync(0xffffffffu, sc2, 2);
                if (tig == 0) {
                    atomicAdd(&s_sc[lr1], sc1);
                    atomicAdd(&s_sc[lr2], sc2);
                }
            }
        }
        if (MODE == 1) {
            __syncthreads();
            // fused softmax numerator: scores are small (weights ~0.05 scale),
            // softmax is shift-invariant -> no segment-max pass needed.
            if (tid < BM) {
                int ge = row0 + tid;
                float ev = expf(s_sc[tid]);
                ex[ge] = ev;
                atomicAdd(&ssum[dst[ge]], ev);
            }
        }
    }
}

// ---------------- weighted aggregation ----------------
template<int DO>
__global__ void aggregate_k(const float* __restrict__ ex, const float* __restrict__ ssum,
                            const float* __restrict__ H, const int* __restrict__ src,
                            const int* __restrict__ dst, float* __restrict__ out, int E) {
    constexpr int L = DO / 4;
    long long gt = (long long)blockIdx.x * blockDim.x + threadIdx.x;
    int e = (int)(gt / L), l = (int)(gt % L);
    if (e >= E) return;
    int dn = dst[e];
    float a = ex[e] / ssum[dn];
    float4 h = *(const float4*)&H[(size_t)src[e] * DO + l * 4];
    float* p = &out[(size_t)dn * DO + l * 4];
    asm volatile("red.global.add.v4.f32 [%0], {%1,%2,%3,%4};"
                 :: "l"(p), "f"(h.x * a), "f"(h.y * a), "f"(h.z * a), "f"(h.w * a)
                 : "memory");
}

// ---------------- host ----------------
static inline constexpr int smemSz(int BN, int KT, int AF32) {
    return (AF32 ? 2 : 3) * 2 * 128 * 48 + 2 * BN * (KT * 2 + 16) + 512;
}

extern "C" void kernel_launch(void* const* d_in, const int* in_sizes, int n_in,
                              void* d_out, int out_size) {
    const float* x    = (const float*)d_in[0];
    const float* e    = (const float*)d_in[1];
    const int*   src  = (const int*)d_in[2];
    const int*   dst  = (const int*)d_in[3];

    const float* W_n1  = (const float*)d_in[4];
    const float* b_n1  = (const float*)d_in[5];
    const float* W_ni1 = (const float*)d_in[6];
    const float* W_nj1 = (const float*)d_in[7];
    const float* W_f1  = (const float*)d_in[8];
    const float* attn1 = (const float*)d_in[9];
    const float* bias1 = (const float*)d_in[10];

    const float* W_n2  = (const float*)d_in[11];
    const float* b_n2  = (const float*)d_in[12];
    const float* W_ni2 = (const float*)d_in[13];
    const float* W_nj2 = (const float*)d_in[14];
    const float* W_f2  = (const float*)d_in[15];
    const float* attn2 = (const float*)d_in[16];
    const float* bias2 = (const float*)d_in[17];

    const float* W_ni3 = (const float*)d_in[20];
    const float* W_nj3 = (const float*)d_in[21];
    const float* W_f3  = (const float*)d_in[22];
    const float* bias3 = (const float*)d_in[24];

    float* out = (float*)d_out;

    float *XNI, *XNJ, *H, *X2, *X3, *ex, *ssum, *bn2, *bias2p, *attn2p;
    __nv_bfloat16 *F1P, *F2P, *wts;
    cudaGetSymbolAddress((void**)&XNI, g_XNI);
    cudaGetSymbolAddress((void**)&XNJ, g_XNJ);
    cudaGetSymbolAddress((void**)&H,   g_H);
    cudaGetSymbolAddress((void**)&X2,  g_X2);
    cudaGetSymbolAddress((void**)&X3,  g_X3);
    cudaGetSymbolAddress((void**)&ex,  g_ex);
    cudaGetSymbolAddress((void**)&ssum, g_ssum);
    cudaGetSymbolAddress((void**)&bn2,  g_bn2);
    cudaGetSymbolAddress((void**)&bias2p, g_bias2);
    cudaGetSymbolAddress((void**)&attn2p, g_attn2);
    cudaGetSymbolAddress((void**)&F1P, g_F1P);
    cudaGetSymbolAddress((void**)&F2P, g_F2P);
    cudaGetSymbolAddress((void**)&wts, g_wts);

    const size_t ePN  = (size_t)EE * 128;
    const size_t F2PN = (size_t)EE * 32;
    const size_t WTN  = 4 * WL1 + 4 * WL2 + 3 * WL3;
    __nv_bfloat16 *wtH = wts, *wtL = wts + WTN;
    const int oWn1 = 0 * WL1, oWni1 = 1 * WL1, oWnj1 = 2 * WL1, oWf1 = 3 * WL1;
    const int base2 = 4 * WL1;
    const int oWn2 = base2, oWni2 = base2 + WL2, oWnj2 = base2 + 2 * WL2, oWf2 = base2 + 3 * WL2;
    const int base3 = base2 + 4 * WL2;
    const int oWni3 = base3, oWnj3 = base3 + WL3, oWf3 = base3 + 2 * WL3;

    const int Nn = NN, Ee = EE;
    const int nodeGrid = (Nn + 127) / 128;
    const int edgeGrid = Ee / 128;

    constexpr int S1  = smemSz(128, 128, 1);
    constexpr int S2n = smemSz(32, 128, 1);
    constexpr int S2e = smemSz(32, 128, 0);
    constexpr int S3n = smemSz(64, 32, 1);
    constexpr int S3e = smemSz(64, 32, 0);
    cudaFuncSetAttribute(gemm_pl<128, 128, 64, 32, 0, 1>, cudaFuncAttributeMaxDynamicSharedMemorySize, S1);
    cudaFuncSetAttribute(gemm_pl<128, 128, 64, 32, 1, 1>, cudaFuncAttributeMaxDynamicSharedMemorySize, S1);
    cudaFuncSetAttribute(gemm_pl<32, 128, 16, 32, 1, 0>, cudaFuncAttributeMaxDynamicSharedMemorySize, S2e);

    // ---- parameter prep ----
    VJobs vj;
    vj.j[0] = {b_n2,  bn2,    30, 32};
    vj.j[1] = {bias2, bias2p, 30, 32};
    vj.j[2] = {attn2, attn2p, 30, 32};
    pad_vec<<<dim3(1, 3), 32>>>(vj);

    WJobs wj;
    wj.j[0]  = {W_n1,  oWn1,  128, 128, 128, 128};
    wj.j[1]  = {W_ni1, oWni1, 128, 128, 128, 128};
    wj.j[2]  = {W_nj1, oWnj1, 128, 128, 128, 128};
    wj.j[3]  = {W_f1,  oWf1,  128, 128, 128, 128};
    wj.j[4]  = {W_n2,  oWn2,  128, 30, 128, 32};
    wj.j[5]  = {W_ni2, oWni2, 128, 30, 128, 32};
    wj.j[6]  = {W_nj2, oWnj2, 128, 30, 128, 32};
    wj.j[7]  = {W_f2,  oWf2,  128, 30, 128, 32};
    wj.j[8]  = {W_ni3, oWni3, 30, 64, 32, 64};
    wj.j[9]  = {W_nj3, oWnj3, 30, 64, 32, 64};
    wj.j[10] = {W_f3,  oWf3,  30, 64, 32, 64};
    conv_wt<<<dim3(64, 11), 256>>>(wj, wtH, wtL);

    // ================= Layer 1 =================
    cudaMemsetAsync(ssum, 0, (size_t)Nn * sizeof(float), 0);
    cudaMemsetAsync(X2,   0, (size_t)Nn * 128 * sizeof(float), 0);
    gemm_pl<128, 128, 64, 32, 0, 1><<<nodeGrid, 256, S1>>>(x, nullptr, wtH + oWni1, wtL + oWni1,
        XNI, nullptr, nullptr, nullptr, nullptr, nullptr, nullptr, nullptr, nullptr, nullptr, nullptr, Nn);
    gemm_pl<128, 128, 64, 32, 0, 1><<<nodeGrid, 256, S1>>>(x, nullptr, wtH + oWnj1, wtL + oWnj1,
        XNJ, nullptr, nullptr, nullptr, nullptr, nullptr, nullptr, nullptr, nullptr, nullptr, nullptr, Nn);
    gemm_pl<128, 128, 64, 32, 0, 1><<<nodeGrid, 256, S1>>>(x, nullptr, wtH + oWn1, wtL + oWn1,
        H, nullptr, nullptr, b_n1, nullptr, nullptr, nullptr, nullptr, nullptr, nullptr, nullptr, Nn);
    gemm_pl<128, 128, 64, 32, 1, 1><<<edgeGrid, 256, S1>>>(e, nullptr, wtH + oWf1, wtL + oWf1,
        nullptr, F1P, F1P + ePN, bias1, XNI, XNJ, src, dst, attn1, ex, ssum, Ee);

    aggregate_k<128><<<((long long)Ee * 32 + 255) / 256, 256>>>(ex, ssum, H, src, dst, X2, Ee);

    // ================= Layer 2 =================
    gemm_pl<32, 128, 16, 32, 0, 1><<<nodeGrid, 256, S2n>>>(X2, nullptr, wtH + oWni2, wtL + oWni2,
        XNI, nullptr, nullptr, nullptr, nullptr, nullptr, nullptr, nullptr, nullptr, nullptr, nullptr, Nn);
    gemm_pl<32, 128, 16, 32, 0, 1><<<nodeGrid, 256, S2n>>>(X2, nullptr, wtH + oWnj2, wtL + oWnj2,
        XNJ, nullptr, nullptr, nullptr, nullptr, nullptr, nullptr, nullptr, nullptr, nullptr, nullptr, Nn);
    gemm_pl<32, 128, 16, 32, 0, 1><<<nodeGrid, 256, S2n>>>(X2, nullptr, wtH + oWn2, wtL + oWn2,
        H, nullptr, nullptr, bn2, nullptr, nullptr, nullptr, nullptr, nullptr, nullptr, nullptr, Nn);
    cudaMemsetAsync(ssum, 0, (size_t)Nn * sizeof(float), 0);
    cudaMemsetAsync(X3,   0, (size_t)Nn * 32 * sizeof(float), 0);
    gemm_pl<32, 128, 16, 32, 1, 0><<<edgeGrid, 256, S2e>>>(F1P, F1P + ePN, wtH + oWf2, wtL + oWf2,
        nullptr, F2P, F2P + F2PN, bias2p, XNI, XNJ, src, dst, attn2p, ex, ssum, Ee);

    aggregate_k<32><<<((long long)Ee * 8 + 255) / 256, 256>>>(ex, ssum, H, src, dst, X3, Ee);

    // ================= Layer 3 (only f) =================
    gemm_pl<64, 32, 32, 32, 0, 1><<<nodeGrid, 256, S3n>>>(X3, nullptr, wtH + oWni3, wtL + oWni3,
        XNI, nullptr, nullptr, nullptr, nullptr, nullptr, nullptr, nullptr, nullptr, nullptr, nullptr, Nn);
    gemm_pl<64, 32, 32, 32, 0, 1><<<nodeGrid, 256, S3n>>>(X3, nullptr, wtH + oWnj3, wtL + oWnj3,
        XNJ, nullptr, nullptr, nullptr, nullptr, nullptr, nullptr, nullptr, nullptr, nullptr, nullptr, Nn);
    gemm_pl<64, 32, 32, 32, 2, 0><<<edgeGrid, 256, S3e>>>(F2P, F2P + F2PN, wtH + oWf3, wtL + oWf3,
        out, nullptr, nullptr, bias3, XNI, XNJ, src, dst, nullptr, nullptr, nullptr, Ee);

    (void)in_sizes; (void)n_in; (void)out_size;
}

// round 14
// speedup vs baseline: 1.4640x; 1.0030x over previous
#include <cuda_runtime.h>
#include <cuda_bf16.h>
#include <cstdint>
#include <cstddef>

#define NN 50000
#define EE 800000

// ---------------- static scratch ----------------
__device__ float g_XNI[(size_t)NN * 128];
__device__ float g_XNJ[(size_t)NN * 128];
__device__ float g_H  [(size_t)NN * 128];
__device__ float g_X2 [(size_t)NN * 128];
__device__ float g_X3 [(size_t)NN * 32];
__device__ float g_ex[EE];
__device__ float g_ssum[NN];
__device__ float g_bn2[32], g_bias2[32], g_attn2[32];

__device__ __nv_bfloat16 g_F1P[2][(size_t)EE * 128];
__device__ __nv_bfloat16 g_F2P[2][(size_t)EE * 32];
#define WL1 (128 * 128)
#define WL2 (32 * 128)
#define WL3 (64 * 32)
__device__ __nv_bfloat16 g_wts[2][4 * WL1 + 4 * WL2 + 3 * WL3];

// ---------------- helpers ----------------
__device__ __forceinline__ uint32_t pk(float a, float b) {
    __nv_bfloat162 h = __floats2bfloat162_rn(a, b);
    return *(uint32_t*)&h;
}
__device__ __forceinline__ float bfe(float v) {
    return __bfloat162float(__float2bfloat16_rn(v));
}
__device__ __forceinline__ void mma16(float d[4], const uint32_t a[4], const uint32_t b[2]) {
    asm volatile(
        "mma.sync.aligned.m16n8k16.row.col.f32.bf16.bf16.f32 "
        "{%0,%1,%2,%3}, {%4,%5,%6,%7}, {%8,%9}, {%0,%1,%2,%3};\n"
        : "+f"(d[0]), "+f"(d[1]), "+f"(d[2]), "+f"(d[3])
        : "r"(a[0]), "r"(a[1]), "r"(a[2]), "r"(a[3]), "r"(b[0]), "r"(b[1]));
}
__device__ __forceinline__ void ldsm4(uint32_t r[4], uint32_t addr) {
    asm volatile("ldmatrix.sync.aligned.m8n8.x4.shared.b16 {%0,%1,%2,%3}, [%4];"
        : "=r"(r[0]), "=r"(r[1]), "=r"(r[2]), "=r"(r[3]) : "r"(addr));
}
__device__ __forceinline__ void ldsm2(uint32_t r[2], uint32_t addr) {
    asm volatile("ldmatrix.sync.aligned.m8n8.x2.shared.b16 {%0,%1}, [%2];"
        : "=r"(r[0]), "=r"(r[1]) : "r"(addr));
}
__device__ __forceinline__ void cpa16(uint32_t saddr, const void* g) {
    asm volatile("cp.async.ca.shared.global [%0], [%1], 16;" :: "r"(saddr), "l"(g));
}
__device__ __forceinline__ void cp_commit() {
    asm volatile("cp.async.commit_group;");
}
template<int N>
__device__ __forceinline__ void cp_wait() {
    asm volatile("cp.async.wait_group %0;" :: "n"(N) : "memory");
}

// ---------------- weight conversion: f32 [K][N] -> transposed planes [Np][Kp] ----------------
struct WJob { const float* w; int off, K, N, Kp, Np; };
struct WJobs { WJob j[11]; };
__global__ void conv_wt(WJobs js, __nv_bfloat16* hiB, __nv_bfloat16* loB) {
    WJob jb = js.j[blockIdx.y];
    int i = blockIdx.x * blockDim.x + threadIdx.x;
    if (i >= jb.Np * jb.Kp) return;
    int n = i / jb.Kp, k = i % jb.Kp;
    float v = (n < jb.N && k < jb.K) ? jb.w[k * jb.N + n] : 0.0f;
    __nv_bfloat16 h = __float2bfloat16_rn(v);
    hiB[jb.off + i] = h;
    loB[jb.off + i] = __float2bfloat16_rn(v - __bfloat162float(h));
}

struct VJob { const float* in; float* out; int C, nC; };
struct VJobs { VJob j[3]; };
__global__ void pad_vec(VJobs js) {
    VJob p = js.j[blockIdx.y];
    int i = threadIdx.x;
    if (i < p.nC) p.out[i] = (i < p.C) ? p.in[i] : 0.0f;
}

// ---------------- GEMM: B smem-resident, k32 super-stages (1 sync / 32k), bf16x3 ----
// A stage buffers: 2 x (2 planes) x 128 rows x 80B (32 bf16 cols; 80B stride is
// 16B-aligned and ldmatrix conflict-free: banks r*20 mod 32 distinct).
// AF32=1: A is f32 [M][K], converted in-kernel. AF32=0: A is bf16 hi/lo planes.
// MODE 0: C = A@B (+bias). MODE 1: F planes + fused exp/segment-sum. MODE 2: C=leaky(...).
template<int BN, int KT, int WM, int WN, int MODE, int AF32>
__global__ __launch_bounds__(256, 2) void gemm_pl(
    const void* __restrict__ Apv, const void* __restrict__ Apv2,
    const __nv_bfloat16* __restrict__ Bhi, const __nv_bfloat16* __restrict__ Blo,
    float* __restrict__ C, __nv_bfloat16* __restrict__ Fhi, __nv_bfloat16* __restrict__ Flo,
    const float* __restrict__ bias,
    const float* __restrict__ XNI, const float* __restrict__ XNJ,
    const int* __restrict__ src, const int* __restrict__ dst,
    const float* __restrict__ attn, float* __restrict__ ex, float* __restrict__ ssum,
    int M)
{
    constexpr int BM = 128;
    constexpr int TS = KT / 32;                // k32 super-stages
    constexpr int AST = 80;                    // A row stride (bytes)
    constexpr int ASZ = 4 * BM * AST;          // 2 buffers x 2 planes
    constexpr int BS = KT * 2 + 16;            // B row stride (bytes)
    constexpr int MT = WM / 16, NT = WN / 8;
    constexpr int WARPS_N = BN / WN;
    static_assert((BM / WM) * (BN / WN) == 8, "need 8 warps");
    static_assert(KT % 32 == 0, "k32 stages");

    extern __shared__ __align__(16) char dynsm[];
    char* sBp = dynsm + ASZ;
    float* s_sc = (float*)(sBp + 2 * BN * BS);

    const int tid  = threadIdx.x;
    const int warp = tid >> 5, lane = tid & 31;
    const int gid  = lane >> 2, tig = lane & 3;
    const int wm   = warp / WARPS_N, wn = warp % WARPS_N;
    const int rowW = wm * WM, colW = wn * WN;
    const int row0 = blockIdx.x * BM;

    const uint32_t aBase = (uint32_t)__cvta_generic_to_shared(dynsm);
    const uint32_t bBase = (uint32_t)__cvta_generic_to_shared(sBp);

    const float* Af = (const float*)Apv;
    const __nv_bfloat16* Ahi = (const __nv_bfloat16*)Apv;
    const __nv_bfloat16* Alo = (const __nv_bfloat16*)Apv2;

    if (MODE == 1 && tid < BM) s_sc[tid] = 0.0f;

    float acc[MT][NT][4];
    #pragma unroll
    for (int i = 0; i < MT; i++)
        #pragma unroll
        for (int j = 0; j < NT; j++)
            #pragma unroll
            for (int t = 0; t < 4; t++) acc[i][j][t] = 0.0f;

    const int lrA = lane & 15;
    const int kofA = ((lane >> 4) & 1) * 16;
    const int lrB = lane & 7;
    const int kofB = ((lane >> 3) & 1) * 16;

    const int arow = tid >> 1, ahalf = tid & 1;
    float areg[8];

    auto issueB = [&]() {
        constexpr int CH = KT / 8;
        #pragma unroll
        for (int c = tid; c < 2 * BN * CH; c += 256) {
            int pl = c / (BN * CH);
            int rem = c - pl * BN * CH;
            int n = rem / CH, ch = rem - n * CH;
            const __nv_bfloat16* g = (pl ? Blo : Bhi) + (size_t)n * KT + ch * 8;
            cpa16(bBase + (uint32_t)((pl * BN + n) * BS + ch * 16), g);
        }
    };
    auto loadAf32 = [&](int t16) {
        int gr = row0 + arow;
        if (gr < M) {
            const float* p = &Af[(size_t)gr * KT + t16 * 16 + ahalf * 8];
            float4 q0 = *(const float4*)p;
            float4 q1 = *(const float4*)(p + 4);
            areg[0] = q0.x; areg[1] = q0.y; areg[2] = q0.z; areg[3] = q0.w;
            areg[4] = q1.x; areg[5] = q1.y; areg[6] = q1.z; areg[7] = q1.w;
        } else {
            #pragma unroll
            for (int u = 0; u < 8; u++) areg[u] = 0.0f;
        }
    };
    // store areg (16 bf16-col substage u of buffer s); thread covers 16B half
    auto stsA = [&](int s, int u) {
        __nv_bfloat16 h[8], l[8];
        #pragma unroll
        for (int v = 0; v < 8; v++) {
            h[v] = __float2bfloat16_rn(areg[v]);
            l[v] = __float2bfloat16_rn(areg[v] - __bfloat162float(h[v]));
        }
        char* base = dynsm;
        *(uint4*)(base + ((s * 2 + 0) * BM + arow) * AST + u * 32 + ahalf * 16) = *(uint4*)h;
        *(uint4*)(base + ((s * 2 + 1) * BM + arow) * AST + u * 32 + ahalf * 16) = *(uint4*)l;
    };
    // plane path: fill 32-col super-stage p into buffer s
    auto issueApl32 = [&](int p, int s) {
        #pragma unroll
        for (int c = tid; c < BM * 8; c += 256) {
            int ch = c & 3, pl = (c >> 2) & 1, r = c >> 3;
            const __nv_bfloat16* g = (pl ? Alo : Ahi) + (size_t)(row0 + r) * KT + p * 32 + ch * 8;
            cpa16(aBase + (uint32_t)(((s * 2 + pl) * BM + r) * AST + ch * 16), g);
        }
    };
    // one k16 substage: u = A col-sub (0/1), t16 = global k16 index (B offset)
    auto mmaSub = [&](int s, int u, int t16) {
        uint32_t ah[MT][4], al[MT][4];
        uint32_t aOff = aBase + (uint32_t)(s * 2 * BM * AST) + (uint32_t)(u * 32);
        #pragma unroll
        for (int i = 0; i < MT; i++) {
            uint32_t ra = aOff + (uint32_t)((rowW + i * 16 + lrA) * AST) + kofA;
            ldsm4(ah[i], ra);
            ldsm4(al[i], ra + (uint32_t)(BM * AST));
        }
        #pragma unroll
        for (int j = 0; j < NT; j++) {
            uint32_t rb = bBase + (uint32_t)((colW + j * 8 + lrB) * BS) + (uint32_t)(t16 * 32) + kofB;
            uint32_t bh[2], bl[2];
            ldsm2(bh, rb);
            ldsm2(bl, rb + (uint32_t)(BN * BS));
            #pragma unroll
            for (int i = 0; i < MT; i++)
                mma16(acc[i][j], ah[i], bh);
            #pragma unroll
            for (int i = 0; i < MT; i++)
                mma16(acc[i][j], ah[i], bl);
            #pragma unroll
            for (int i = 0; i < MT; i++)
                mma16(acc[i][j], al[i], bh);
        }
    };

    if (AF32) {
        issueB(); cp_commit();
        loadAf32(0); stsA(0, 0);
        loadAf32(1); stsA(0, 1);
        cp_wait<0>();
        __syncthreads();
        for (int p = 0; p < TS; p++) {
            int s = p & 1;
            if (p + 1 < TS) loadAf32(2 * p + 2);
            mmaSub(s, 0, 2 * p);
            if (p + 1 < TS) { stsA(1 - s, 0); loadAf32(2 * p + 3); }
            mmaSub(s, 1, 2 * p + 1);
            if (p + 1 < TS) stsA(1 - s, 1);
            __syncthreads();
        }
    } else {
        issueB(); issueApl32(0, 0); cp_commit();
        for (int p = 0; p < TS; p++) {
            int s = p & 1;
            if (p + 1 < TS) { issueApl32(p + 1, 1 - s); cp_commit(); cp_wait<1>(); }
            else cp_wait<0>();
            __syncthreads();
            mmaSub(s, 0, 2 * p);
            mmaSub(s, 1, 2 * p + 1);
            __syncthreads();
        }
    }

    // ---------------- epilogue ----------------
    if (MODE == 0) {
        #pragma unroll
        for (int i = 0; i < MT; i++) {
            int gr1 = row0 + rowW + i * 16 + gid;
            int gr2 = gr1 + 8;
            #pragma unroll
            for (int j = 0; j < NT; j++) {
                int c = colW + j * 8 + 2 * tig;
                float b0 = bias ? bias[c] : 0.0f;
                float b1 = bias ? bias[c + 1] : 0.0f;
                if (gr1 < M)
                    *(float2*)&C[(size_t)gr1 * BN + c] =
                        make_float2(acc[i][j][0] + b0, acc[i][j][1] + b1);
                if (gr2 < M)
                    *(float2*)&C[(size_t)gr2 * BN + c] =
                        make_float2(acc[i][j][2] + b0, acc[i][j][3] + b1);
            }
        }
    } else {
        #pragma unroll
        for (int i = 0; i < MT; i++) {
            int lr1 = rowW + i * 16 + gid, lr2 = lr1 + 8;
            int gr1 = row0 + lr1, gr2 = row0 + lr2;
            int sn1 = src[gr1], dn1 = dst[gr1];
            int sn2 = src[gr2], dn2 = dst[gr2];
            float sc1 = 0.0f, sc2 = 0.0f;
            #pragma unroll
            for (int j = 0; j < NT; j++) {
                int c = colW + j * 8 + 2 * tig;
                float b0 = bias[c], b1 = bias[c + 1];
                float2 xi1 = *(const float2*)&XNI[(size_t)sn1 * BN + c];
                float2 xj1 = *(const float2*)&XNJ[(size_t)dn1 * BN + c];
                float o0 = acc[i][j][0] + xi1.x + xj1.x + b0;
                float o1 = acc[i][j][1] + xi1.y + xj1.y + b1;
                o0 = o0 > 0.f ? o0 : 0.01f * o0;
                o1 = o1 > 0.f ? o1 : 0.01f * o1;
                float2 xi2 = *(const float2*)&XNI[(size_t)sn2 * BN + c];
                float2 xj2 = *(const float2*)&XNJ[(size_t)dn2 * BN + c];
                float p0 = acc[i][j][2] + xi2.x + xj2.x + b0;
                float p1 = acc[i][j][3] + xi2.y + xj2.y + b1;
                p0 = p0 > 0.f ? p0 : 0.01f * p0;
                p1 = p1 > 0.f ? p1 : 0.01f * p1;
                if (MODE == 1) {
                    *(uint32_t*)&Fhi[(size_t)gr1 * BN + c] = pk(o0, o1);
                    *(uint32_t*)&Flo[(size_t)gr1 * BN + c] = pk(o0 - bfe(o0), o1 - bfe(o1));
                    *(uint32_t*)&Fhi[(size_t)gr2 * BN + c] = pk(p0, p1);
                    *(uint32_t*)&Flo[(size_t)gr2 * BN + c] = pk(p0 - bfe(p0), p1 - bfe(p1));
                    float a0 = attn[c], a1 = attn[c + 1];
                    sc1 += o0 * a0 + o1 * a1;
                    sc2 += p0 * a0 + p1 * a1;
                } else {
                    *(float2*)&C[(size_t)gr1 * BN + c] = make_float2(o0, o1);
                    *(float2*)&C[(size_t)gr2 * BN + c] = make_float2(p0, p1);
                }
            }
            if (MODE == 1) {
                sc1 += __shfl_xor_sync(0xffffffffu, sc1, 1);
                sc1 += __shfl_xor_sync(0xffffffffu, sc1, 2);
                sc2 += __shfl_xor_sync(0xffffffffu, sc2, 1);
                sc2 += __shfl_xor_sync(0xffffffffu, sc2, 2);
                if (tig == 0) {
                    atomicAdd(&s_sc[lr1], sc1);
                    atomicAdd(&s_sc[lr2], sc2);
                }
            }
        }
        if (MODE == 1) {
            __syncthreads();
            // scores are small; softmax is shift-invariant -> no segment-max needed
            if (tid < BM) {
                int ge = row0 + tid;
                float ev = expf(s_sc[tid]);
                ex[ge] = ev;
                atomicAdd(&ssum[dst[ge]], ev);
            }
        }
    }
}

// ---------------- softmax coefficient: ex[e] <- ex[e] / ssum[dst[e]] ----------------
__global__ void coef_k(float* __restrict__ ex, const float* __restrict__ ssum,
                       const int* __restrict__ dst, int E) {
    int e = blockIdx.x * blockDim.x + threadIdx.x;
    if (e >= E) return;
    ex[e] = ex[e] / ssum[dst[e]];
}

// ---------------- weighted aggregation: out[dst] += a * H[src] ----------------
template<int DO>
__global__ void aggregate_k(const float* __restrict__ a, const float* __restrict__ H,
                            const int* __restrict__ src, const int* __restrict__ dst,
                            float* __restrict__ out, int E) {
    constexpr int L = DO / 4;
    long long gt = (long long)blockIdx.x * blockDim.x + threadIdx.x;
    int e = (int)(gt / L), l = (int)(gt % L);
    if (e >= E) return;
    float av = a[e];
    float4 h = *(const float4*)&H[(size_t)src[e] * DO + l * 4];
    float* p = &out[(size_t)dst[e] * DO + l * 4];
    asm volatile("red.global.add.v4.f32 [%0], {%1,%2,%3,%4};"
                 :: "l"(p), "f"(h.x * av), "f"(h.y * av), "f"(h.z * av), "f"(h.w * av)
                 : "memory");
}

// ---------------- host ----------------
static inline constexpr int smemSz(int BN, int KT) {
    return 4 * 128 * 80 + 2 * BN * (KT * 2 + 16) + 512;
}

extern "C" void kernel_launch(void* const* d_in, const int* in_sizes, int n_in,
                              void* d_out, int out_size) {
    const float* x    = (const float*)d_in[0];
    const float* e    = (const float*)d_in[1];
    const int*   src  = (const int*)d_in[2];
    const int*   dst  = (const int*)d_in[3];

    const float* W_n1  = (const float*)d_in[4];
    const float* b_n1  = (const float*)d_in[5];
    const float* W_ni1 = (const float*)d_in[6];
    const float* W_nj1 = (const float*)d_in[7];
    const float* W_f1  = (const float*)d_in[8];
    const float* attn1 = (const float*)d_in[9];
    const float* bias1 = (const float*)d_in[10];

    const float* W_n2  = (const float*)d_in[11];
    const float* b_n2  = (const float*)d_in[12];
    const float* W_ni2 = (const float*)d_in[13];
    const float* W_nj2 = (const float*)d_in[14];
    const float* W_f2  = (const float*)d_in[15];
    const float* attn2 = (const float*)d_in[16];
    const float* bias2 = (const float*)d_in[17];

    const float* W_ni3 = (const float*)d_in[20];
    const float* W_nj3 = (const float*)d_in[21];
    const float* W_f3  = (const float*)d_in[22];
    const float* bias3 = (const float*)d_in[24];

    float* out = (float*)d_out;

    float *XNI, *XNJ, *H, *X2, *X3, *ex, *ssum, *bn2, *bias2p, *attn2p;
    __nv_bfloat16 *F1P, *F2P, *wts;
    cudaGetSymbolAddress((void**)&XNI, g_XNI);
    cudaGetSymbolAddress((void**)&XNJ, g_XNJ);
    cudaGetSymbolAddress((void**)&H,   g_H);
    cudaGetSymbolAddress((void**)&X2,  g_X2);
    cudaGetSymbolAddress((void**)&X3,  g_X3);
    cudaGetSymbolAddress((void**)&ex,  g_ex);
    cudaGetSymbolAddress((void**)&ssum, g_ssum);
    cudaGetSymbolAddress((void**)&bn2,  g_bn2);
    cudaGetSymbolAddress((void**)&bias2p, g_bias2);
    cudaGetSymbolAddress((void**)&attn2p, g_attn2);
    cudaGetSymbolAddress((void**)&F1P, g_F1P);
    cudaGetSymbolAddress((void**)&F2P, g_F2P);
    cudaGetSymbolAddress((void**)&wts, g_wts);

    const size_t ePN  = (size_t)EE * 128;
    const size_t F2PN = (size_t)EE * 32;
    const size_t WTN  = 4 * WL1 + 4 * WL2 + 3 * WL3;
    __nv_bfloat16 *wtH = wts, *wtL = wts + WTN;
    const int oWn1 = 0 * WL1, oWni1 = 1 * WL1, oWnj1 = 2 * WL1, oWf1 = 3 * WL1;
    const int base2 = 4 * WL1;
    const int oWn2 = base2, oWni2 = base2 + WL2, oWnj2 = base2 + 2 * WL2, oWf2 = base2 + 3 * WL2;
    const int base3 = base2 + 4 * WL2;
    const int oWni3 = base3, oWnj3 = base3 + WL3, oWf3 = base3 + 2 * WL3;

    const int Nn = NN, Ee = EE;
    const int nodeGrid = (Nn + 127) / 128;
    const int edgeGrid = Ee / 128;
    const int perThread = (Ee + 255) / 256;

    constexpr int S1  = smemSz(128, 128);   // 111,104
    constexpr int S2  = smemSz(32, 128);
    constexpr int S3  = smemSz(64, 32);
    cudaFuncSetAttribute(gemm_pl<128, 128, 64, 32, 0, 1>, cudaFuncAttributeMaxDynamicSharedMemorySize, S1);
    cudaFuncSetAttribute(gemm_pl<128, 128, 64, 32, 1, 1>, cudaFuncAttributeMaxDynamicSharedMemorySize, S1);
    cudaFuncSetAttribute(gemm_pl<32, 128, 16, 32, 0, 1>, cudaFuncAttributeMaxDynamicSharedMemorySize, S2);
    cudaFuncSetAttribute(gemm_pl<32, 128, 16, 32, 1, 0>, cudaFuncAttributeMaxDynamicSharedMemorySize, S2);
    cudaFuncSetAttribute(gemm_pl<64, 32, 32, 32, 0, 1>, cudaFuncAttributeMaxDynamicSharedMemorySize, S3);
    cudaFuncSetAttribute(gemm_pl<64, 32, 32, 32, 2, 0>, cudaFuncAttributeMaxDynamicSharedMemorySize, S3);

    // ---- parameter prep ----
    VJobs vj;
    vj.j[0] = {b_n2,  bn2,    30, 32};
    vj.j[1] = {bias2, bias2p, 30, 32};
    vj.j[2] = {attn2, attn2p, 30, 32};
    pad_vec<<<dim3(1, 3), 32>>>(vj);

    WJobs wj;
    wj.j[0]  = {W_n1,  oWn1,  128, 128, 128, 128};
    wj.j[1]  = {W_ni1, oWni1, 128, 128, 128, 128};
    wj.j[2]  = {W_nj1, oWnj1, 128, 128, 128, 128};
    wj.j[3]  = {W_f1,  oWf1,  128, 128, 128, 128};
    wj.j[4]  = {W_n2,  oWn2,  128, 30, 128, 32};
    wj.j[5]  = {W_ni2, oWni2, 128, 30, 128, 32};
    wj.j[6]  = {W_nj2, oWnj2, 128, 30, 128, 32};
    wj.j[7]  = {W_f2,  oWf2,  128, 30, 128, 32};
    wj.j[8]  = {W_ni3, oWni3, 30, 64, 32, 64};
    wj.j[9]  = {W_nj3, oWnj3, 30, 64, 32, 64};
    wj.j[10] = {W_f3,  oWf3,  30, 64, 32, 64};
    conv_wt<<<dim3(64, 11), 256>>>(wj, wtH, wtL);

    // ================= Layer 1 =================
    cudaMemsetAsync(ssum, 0, (size_t)Nn * sizeof(float), 0);
    cudaMemsetAsync(X2,   0, (size_t)Nn * 128 * sizeof(float), 0);
    gemm_pl<128, 128, 64, 32, 0, 1><<<nodeGrid, 256, S1>>>(x, nullptr, wtH + oWni1, wtL + oWni1,
        XNI, nullptr, nullptr, nullptr, nullptr, nullptr, nullptr, nullptr, nullptr, nullptr, nullptr, Nn);
    gemm_pl<128, 128, 64, 32, 0, 1><<<nodeGrid, 256, S1>>>(x, nullptr, wtH + oWnj1, wtL + oWnj1,
        XNJ, nullptr, nullptr, nullptr, nullptr, nullptr, nullptr, nullptr, nullptr, nullptr, nullptr, Nn);
    gemm_pl<128, 128, 64, 32, 0, 1><<<nodeGrid, 256, S1>>>(x, nullptr, wtH + oWn1, wtL + oWn1,
        H, nullptr, nullptr, b_n1, nullptr, nullptr, nullptr, nullptr, nullptr, nullptr, nullptr, Nn);
    gemm_pl<128, 128, 64, 32, 1, 1><<<edgeGrid, 256, S1>>>(e, nullptr, wtH + oWf1, wtL + oWf1,
        nullptr, F1P, F1P + ePN, bias1, XNI, XNJ, src, dst, attn1, ex, ssum, Ee);

    coef_k<<<perThread, 256>>>(ex, ssum, dst, Ee);
    aggregate_k<128><<<((long long)Ee * 32 + 255) / 256, 256>>>(ex, H, src, dst, X2, Ee);

    // ================= Layer 2 =================
    gemm_pl<32, 128, 16, 32, 0, 1><<<nodeGrid, 256, S2>>>(X2, nullptr, wtH + oWni2, wtL + oWni2,
        XNI, nullptr, nullptr, nullptr, nullptr, nullptr, nullptr, nullptr, nullptr, nullptr, nullptr, Nn);
    gemm_pl<32, 128, 16, 32, 0, 1><<<nodeGrid, 256, S2>>>(X2, nullptr, wtH + oWnj2, wtL + oWnj2,
        XNJ, nullptr, nullptr, nullptr, nullptr, nullptr, nullptr, nullptr, nullptr, nullptr, nullptr, Nn);
    gemm_pl<32, 128, 16, 32, 0, 1><<<nodeGrid, 256, S2>>>(X2, nullptr, wtH + oWn2, wtL + oWn2,
        H, nullptr, nullptr, bn2, nullptr, nullptr, nullptr, nullptr, nullptr, nullptr, nullptr, Nn);
    cudaMemsetAsync(ssum, 0, (size_t)Nn * sizeof(float), 0);
    cudaMemsetAsync(X3,   0, (size_t)Nn * 32 * sizeof(float), 0);
    gemm_pl<32, 128, 16, 32, 1, 0><<<edgeGrid, 256, S2>>>(F1P, F1P + ePN, wtH + oWf2, wtL + oWf2,
        nullptr, F2P, F2P + F2PN, bias2p, XNI, XNJ, src, dst, attn2p, ex, ssum, Ee);

    coef_k<<<perThread, 256>>>(ex, ssum, dst, Ee);
    aggregate_k<32><<<((long long)Ee * 8 + 255) / 256, 256>>>(ex, H, src, dst, X3, Ee);

    // ================= Layer 3 (only f) =================
    gemm_pl<64, 32, 32, 32, 0, 1><<<nodeGrid, 256, S3>>>(X3, nullptr, wtH + oWni3, wtL + oWni3,
        XNI, nullptr, nullptr, nullptr, nullptr, nullptr, nullptr, nullptr, nullptr, nullptr, nullptr, Nn);
    gemm_pl<64, 32, 32, 32, 0, 1><<<nodeGrid, 256, S3>>>(X3, nullptr, wtH + oWnj3, wtL + oWnj3,
        XNJ, nullptr, nullptr, nullptr, nullptr, nullptr, nullptr, nullptr, nullptr, nullptr, nullptr, Nn);
    gemm_pl<64, 32, 32, 32, 2, 0><<<edgeGrid, 256, S3>>>(F2P, F2P + F2PN, wtH + oWf3, wtL + oWf3,
        out, nullptr, nullptr, bias3, XNI, XNJ, src, dst, nullptr, nullptr, nullptr, Ee);

    (void)in_sizes; (void)n_in; (void)out_size;
}